// round 1
// baseline (speedup 1.0000x reference)
#include <cuda_runtime.h>

#define BB 4
#define LL 4096
#define DD 768

// Scratch (allocation-free contract: __device__ globals)
__device__ float g_Q[(size_t)BB * LL * DD];           // 48 MB
__device__ float g_K[(size_t)BB * LL * DD];           // 48 MB
__device__ float g_V[(size_t)BB * LL * DD];           // 48 MB
__device__ float g_S[(size_t)BB * LL * LL];           // 256 MB

// ---------------------------------------------------------------------------
// Classic 128x128x8 register-blocked SGEMM, 256 threads, 8x8 per thread.
// TRANSB=false: C[M,N] = A[M,K] * B[K,N] (+bias)     (row-major)
// TRANSB=true : C[M,N] = A[M,K] * B[N,K]^T           (row-major)
// blockIdx.z = batch, with element strides sA/sB/sC.
// All of M, N are multiples of 128 and K a multiple of 8 for our shapes,
// so no bounds checks are needed.
// ---------------------------------------------------------------------------
template <bool TRANSB, bool HASBIAS>
__global__ void __launch_bounds__(256, 2)
gemm128(const float* __restrict__ A, const float* __restrict__ Bm,
        const float* __restrict__ bias, float* __restrict__ C,
        int M, int N, int K,
        long long sA, long long sB, long long sC)
{
    A  += (long long)blockIdx.z * sA;
    Bm += (long long)blockIdx.z * sB;
    C  += (long long)blockIdx.z * sC;

    __shared__ float As[8][128];
    __shared__ float Bs[8][128];

    const int tid = threadIdx.x;
    const int ty  = tid >> 4;    // 0..15 -> row group
    const int tx  = tid & 15;    // 0..15 -> col group

    const int m0 = blockIdx.y * 128;
    const int n0 = blockIdx.x * 128;

    // Loader mapping for [128 rows x 8 cols] tiles (A always; B when TRANSB)
    const int lr = tid >> 1;           // 0..127
    const int lc = (tid & 1) * 4;      // 0 or 4

    float acc[8][8];
#pragma unroll
    for (int i = 0; i < 8; i++)
#pragma unroll
        for (int j = 0; j < 8; j++) acc[i][j] = 0.0f;

    for (int kt = 0; kt < K; kt += 8) {
        // A tile: 128 rows x 8 k  -> transposed into As[k][m]
        float4 av = *(const float4*)(A + (long long)(m0 + lr) * K + kt + lc);
        As[lc + 0][lr] = av.x;
        As[lc + 1][lr] = av.y;
        As[lc + 2][lr] = av.z;
        As[lc + 3][lr] = av.w;

        if (TRANSB) {
            // B tile: 128 n-rows x 8 k -> Bs[k][n]
            float4 bv = *(const float4*)(Bm + (long long)(n0 + lr) * K + kt + lc);
            Bs[lc + 0][lr] = bv.x;
            Bs[lc + 1][lr] = bv.y;
            Bs[lc + 2][lr] = bv.z;
            Bs[lc + 3][lr] = bv.w;
        } else {
            // B tile: 8 k-rows x 128 n (contiguous) -> Bs[k][n]
            const int br = tid >> 5;          // 0..7
            const int bc = (tid & 31) * 4;    // 0..124
            *(float4*)&Bs[br][bc] =
                *(const float4*)(Bm + (long long)(kt + br) * N + n0 + bc);
        }
        __syncthreads();

#pragma unroll
        for (int k = 0; k < 8; k++) {
            float a[8], b[8];
#pragma unroll
            for (int i = 0; i < 8; i++) a[i] = As[k][ty * 8 + i];
#pragma unroll
            for (int j = 0; j < 8; j++) b[j] = Bs[k][tx * 8 + j];
#pragma unroll
            for (int i = 0; i < 8; i++)
#pragma unroll
                for (int j = 0; j < 8; j++)
                    acc[i][j] = fmaf(a[i], b[j], acc[i][j]);
        }
        __syncthreads();
    }

#pragma unroll
    for (int i = 0; i < 8; i++) {
        long long row = m0 + ty * 8 + i;
        float* cp = C + row * (long long)N + n0 + tx * 8;
#pragma unroll
        for (int j = 0; j < 8; j += 4) {
            float4 v;
            v.x = acc[i][j + 0];
            v.y = acc[i][j + 1];
            v.z = acc[i][j + 2];
            v.w = acc[i][j + 3];
            if (HASBIAS) {
                const float* bp = bias + n0 + tx * 8 + j;
                v.x += bp[0]; v.y += bp[1]; v.z += bp[2]; v.w += bp[3];
            }
            *(float4*)(cp + j) = v;
        }
    }
}

// ---------------------------------------------------------------------------
// Row softmax over rows of length LL=4096, in place. One block per row.
// Row is staged in shared memory (16 KB) so global traffic is 1R + 1W.
// ---------------------------------------------------------------------------
__global__ void __launch_bounds__(256)
softmax4096(float* __restrict__ S)
{
    __shared__ float sh[LL];
    __shared__ float red[256];

    float* p = S + (long long)blockIdx.x * LL;
    const int tid = threadIdx.x;

    float m = -3.402823466e38f;
#pragma unroll
    for (int i = 0; i < LL / (256 * 4); i++) {
        int idx = (i * 256 + tid) * 4;
        float4 v = *(const float4*)(p + idx);
        *(float4*)&sh[idx] = v;
        m = fmaxf(m, fmaxf(fmaxf(v.x, v.y), fmaxf(v.z, v.w)));
    }
    red[tid] = m;
    __syncthreads();
#pragma unroll
    for (int s = 128; s > 0; s >>= 1) {
        if (tid < s) red[tid] = fmaxf(red[tid], red[tid + s]);
        __syncthreads();
    }
    m = red[0];
    __syncthreads();

    float sum = 0.0f;
#pragma unroll
    for (int i = 0; i < LL / (256 * 4); i++) {
        int idx = (i * 256 + tid) * 4;
        float4 v = *(float4*)&sh[idx];
        v.x = __expf(v.x - m);
        v.y = __expf(v.y - m);
        v.z = __expf(v.z - m);
        v.w = __expf(v.w - m);
        *(float4*)&sh[idx] = v;
        sum += v.x + v.y + v.z + v.w;
    }
    red[tid] = sum;
    __syncthreads();
#pragma unroll
    for (int s = 128; s > 0; s >>= 1) {
        if (tid < s) red[tid] += red[tid + s];
        __syncthreads();
    }
    const float inv = 1.0f / red[0];
    __syncthreads();

#pragma unroll
    for (int i = 0; i < LL / (256 * 4); i++) {
        int idx = (i * 256 + tid) * 4;
        float4 v = *(float4*)&sh[idx];
        v.x *= inv; v.y *= inv; v.z *= inv; v.w *= inv;
        *(float4*)(p + idx) = v;
    }
}

// ---------------------------------------------------------------------------
// Orchestration: Q/K/V projections -> batched S=QK^T -> row softmax -> O=PV
// ---------------------------------------------------------------------------
extern "C" void kernel_launch(void* const* d_in, const int* in_sizes, int n_in,
                              void* d_out, int out_size)
{
    const float* X  = (const float*)d_in[0];
    const float* Wq = (const float*)d_in[1];
    const float* bq = (const float*)d_in[2];
    const float* Wk = (const float*)d_in[3];
    const float* bk = (const float*)d_in[4];
    const float* Wv = (const float*)d_in[5];
    const float* bv = (const float*)d_in[6];
    float* out = (float*)d_out;

    float *Q, *K, *V, *S;
    cudaGetSymbolAddress((void**)&Q, g_Q);
    cudaGetSymbolAddress((void**)&K, g_K);
    cudaGetSymbolAddress((void**)&V, g_V);
    cudaGetSymbolAddress((void**)&S, g_S);

    dim3 blk(256);

    // 1) Projections: [16384,768] = X[16384,768] @ W[768,768] + b
    {
        dim3 grid(DD / 128, (BB * LL) / 128, 1);
        gemm128<false, true><<<grid, blk>>>(X, Wq, bq, Q, BB * LL, DD, DD, 0, 0, 0);
        gemm128<false, true><<<grid, blk>>>(X, Wk, bk, K, BB * LL, DD, DD, 0, 0, 0);
        gemm128<false, true><<<grid, blk>>>(X, Wv, bv, V, BB * LL, DD, DD, 0, 0, 0);
    }

    // 2) Logits: per batch, S[4096,4096] = Q[4096,768] @ K[4096,768]^T
    {
        dim3 grid(LL / 128, LL / 128, BB);
        gemm128<true, false><<<grid, blk>>>(Q, K, nullptr, S, LL, LL, DD,
                                            (long long)LL * DD,
                                            (long long)LL * DD,
                                            (long long)LL * LL);
    }

    // 3) Row softmax over all B*L rows, in place
    softmax4096<<<BB * LL, blk>>>(S);

    // 4) Output: per batch, O[4096,768] = P[4096,4096] @ V[4096,768]
    {
        dim3 grid(DD / 128, LL / 128, BB);
        gemm128<false, false><<<grid, blk>>>(S, V, nullptr, out, LL, DD, LL,
                                             (long long)LL * LL,
                                             (long long)LL * DD,
                                             (long long)LL * DD);
    }
}

// round 3
// speedup vs baseline: 3.2327x; 3.2327x over previous
#include <cuda_runtime.h>
#include <cuda_bf16.h>
#include <cstdint>

#define BB 4
#define LL 4096
#define DD 768
#define ML (BB*LL)

// ---------------- scratch (__device__ globals; allocation-free contract) ----
__device__ __nv_bfloat16 g_Xh[(size_t)ML * DD], g_Xl[(size_t)ML * DD];
__device__ __nv_bfloat16 g_Wth[3][(size_t)DD * DD], g_Wtl[3][(size_t)DD * DD];
__device__ __nv_bfloat16 g_Qh[(size_t)ML * DD], g_Ql[(size_t)ML * DD];
__device__ __nv_bfloat16 g_Kh[(size_t)ML * DD], g_Kl[(size_t)ML * DD];
__device__ __nv_bfloat16 g_Vh[(size_t)ML * DD], g_Vl[(size_t)ML * DD];
__device__ __nv_bfloat16 g_Vth[(size_t)ML * DD], g_Vtl[(size_t)ML * DD];
__device__ float         g_S [(size_t)BB * LL * LL];
__device__ __nv_bfloat16 g_Ph[(size_t)BB * LL * LL], g_Pl[(size_t)BB * LL * LL];

// ---------------- helpers (base-family ISA only: cp.async/ldmatrix/mma) -----
__device__ __forceinline__ uint32_t s2u(const void* p) {
    uint32_t a;
    asm("{ .reg .u64 t; cvta.to.shared.u64 t, %1; cvt.u32.u64 %0, t; }"
        : "=r"(a) : "l"(p));
    return a;
}
__device__ __forceinline__ uint32_t sw128(uint32_t off) {
    return off ^ ((off >> 3) & 0x70);
}
__device__ __forceinline__ void cp16(uint32_t saddr, const void* g) {
    asm volatile("cp.async.cg.shared.global [%0], [%1], 16;" :: "r"(saddr), "l"(g));
}
__device__ __forceinline__ void cp_commit() {
    asm volatile("cp.async.commit_group;");
}
template <int N>
__device__ __forceinline__ void cp_wait() {
    asm volatile("cp.async.wait_group %0;" :: "n"(N));
}
__device__ __forceinline__ void ldm_x4(uint32_t* r, uint32_t addr) {
    asm volatile("ldmatrix.sync.aligned.m8n8.x4.shared.b16 {%0,%1,%2,%3}, [%4];"
                 : "=r"(r[0]), "=r"(r[1]), "=r"(r[2]), "=r"(r[3]) : "r"(addr));
}
__device__ __forceinline__ void ldm_x2(uint32_t* r, uint32_t addr) {
    asm volatile("ldmatrix.sync.aligned.m8n8.x2.shared.b16 {%0,%1}, [%2];"
                 : "=r"(r[0]), "=r"(r[1]) : "r"(addr));
}
__device__ __forceinline__ void mma_bf16(float* c, const uint32_t* a, const uint32_t* b) {
    asm volatile(
        "mma.sync.aligned.m16n8k16.row.col.f32.bf16.bf16.f32 "
        "{%0,%1,%2,%3}, {%4,%5,%6,%7}, {%8,%9}, {%0,%1,%2,%3};"
        : "+f"(c[0]), "+f"(c[1]), "+f"(c[2]), "+f"(c[3])
        : "r"(a[0]), "r"(a[1]), "r"(a[2]), "r"(a[3]), "r"(b[0]), "r"(b[1]));
}

// ---------------- bf16x3 HMMA GEMM: C[M,N] = sum_k A[m,k]*B[n,k] ------------
// A,B: K-major bf16 hi/lo pairs with row stride K. 128x128 CTA tile,
// 64-k chunks, cp.async double buffer, SW128-swizzled SMEM.
// EPI=0: +bias, write bf16 hi/lo to C0/C1 (ld = ldC).
// EPI=2: write fp32 to C0 (+z*strC).
static constexpr int STAGE_BYTES = 65536;              // 4 x 16KB (Ah,Al,Bh,Bl)
static constexpr int SMEM_BYTES  = 2 * STAGE_BYTES;    // 128 KB

__device__ __forceinline__ void load_tile64(const __nv_bfloat16* __restrict__ g,
                                            long long ld, uint32_t sdst, int tid) {
#pragma unroll
    for (int it = 0; it < 4; it++) {
        int u = it * 256 + tid;            // 0..1023: 128 rows x 8 16B-segments
        int row = u >> 3, seg = u & 7;
        cp16(sdst + sw128(row * 128 + seg * 16), g + (long long)row * ld + seg * 8);
    }
}

template <int EPI>
__global__ void __launch_bounds__(256, 1)
gemm_mma(const __nv_bfloat16* __restrict__ Ah, const __nv_bfloat16* __restrict__ Al,
         const __nv_bfloat16* __restrict__ Bh, const __nv_bfloat16* __restrict__ Bl,
         const float* __restrict__ bias,
         void* __restrict__ C0, void* __restrict__ C1,
         int K, int ldC,
         long long strA, long long strB, long long strC)
{
    extern __shared__ char smem[];
    const uint32_t sbase = s2u(smem);
    const int tid  = threadIdx.x;
    const int lane = tid & 31;
    const int warp = tid >> 5;
    const int wm = warp >> 1;   // 0..3
    const int wn = warp & 1;    // 0..1
    const int m0 = blockIdx.y * 128, n0 = blockIdx.x * 128;
    const long long z = blockIdx.z;

    const __nv_bfloat16* aH = Ah + z * strA + (long long)m0 * K;
    const __nv_bfloat16* aL = Al + z * strA + (long long)m0 * K;
    const __nv_bfloat16* bH = Bh + z * strB + (long long)n0 * K;
    const __nv_bfloat16* bL = Bl + z * strB + (long long)n0 * K;

    float acc[2][8][4];
#pragma unroll
    for (int mt = 0; mt < 2; mt++)
#pragma unroll
        for (int nt = 0; nt < 8; nt++)
#pragma unroll
            for (int i = 0; i < 4; i++) acc[mt][nt][i] = 0.0f;

    const int nch = K >> 6;

    // prologue: chunk 0
    {
        uint32_t sb = sbase;
        load_tile64(aH, K, sb,         tid);
        load_tile64(aL, K, sb + 16384, tid);
        load_tile64(bH, K, sb + 32768, tid);
        load_tile64(bL, K, sb + 49152, tid);
        cp_commit();
    }

    for (int c = 0; c < nch; c++) {
        if (c + 1 < nch) {
            uint32_t sb = sbase + ((c + 1) & 1) * STAGE_BYTES;
            load_tile64(aH + (c + 1) * 64, K, sb,         tid);
            load_tile64(aL + (c + 1) * 64, K, sb + 16384, tid);
            load_tile64(bH + (c + 1) * 64, K, sb + 32768, tid);
            load_tile64(bL + (c + 1) * 64, K, sb + 49152, tid);
            cp_commit();
            cp_wait<1>();
        } else {
            cp_wait<0>();
        }
        __syncthreads();

        const uint32_t sb  = sbase + (c & 1) * STAGE_BYTES;
        const uint32_t sAh = sb, sAl = sb + 16384, sBh = sb + 32768, sBl = sb + 49152;

#pragma unroll
        for (int ks = 0; ks < 4; ks++) {
            uint32_t ah[2][4], al[2][4];
#pragma unroll
            for (int mt = 0; mt < 2; mt++) {
                uint32_t off = sw128((uint32_t)((wm * 32 + mt * 16 + (lane & 15)) * 128
                                                + (ks * 2 + (lane >> 4)) * 16));
                ldm_x4(ah[mt], sAh + off);
                ldm_x4(al[mt], sAl + off);
            }
#pragma unroll
            for (int nt = 0; nt < 8; nt++) {
                uint32_t boff = sw128((uint32_t)((wn * 64 + nt * 8 + (lane & 7)) * 128
                                                 + (ks * 2 + ((lane >> 3) & 1)) * 16));
                uint32_t bh[2], bl[2];
                ldm_x2(bh, sBh + boff);
                ldm_x2(bl, sBl + boff);
#pragma unroll
                for (int mt = 0; mt < 2; mt++) {
                    mma_bf16(acc[mt][nt], ah[mt], bh);
                    mma_bf16(acc[mt][nt], ah[mt], bl);
                    mma_bf16(acc[mt][nt], al[mt], bh);
                }
            }
        }
        __syncthreads();
    }

    // ----- epilogue -----
    const int rbase = m0 + wm * 32 + (lane >> 2);
    const int cbase = n0 + wn * 64 + 2 * (lane & 3);
    if (EPI == 0) {
        __nv_bfloat16* Ch = (__nv_bfloat16*)C0;
        __nv_bfloat16* Cl = (__nv_bfloat16*)C1;
#pragma unroll
        for (int mt = 0; mt < 2; mt++)
#pragma unroll
            for (int nt = 0; nt < 8; nt++) {
                int col = cbase + nt * 8;
                float b0 = bias[col], b1 = bias[col + 1];
#pragma unroll
                for (int half = 0; half < 2; half++) {
                    int r = rbase + mt * 16 + half * 8;
                    float v0 = acc[mt][nt][half * 2 + 0] + b0;
                    float v1 = acc[mt][nt][half * 2 + 1] + b1;
                    __nv_bfloat16 h0 = __float2bfloat16(v0);
                    __nv_bfloat16 h1 = __float2bfloat16(v1);
                    __nv_bfloat16 l0 = __float2bfloat16(v0 - __bfloat162float(h0));
                    __nv_bfloat16 l1 = __float2bfloat16(v1 - __bfloat162float(h1));
                    *(__nv_bfloat162*)(Ch + (size_t)r * ldC + col) = __halves2bfloat162(h0, h1);
                    *(__nv_bfloat162*)(Cl + (size_t)r * ldC + col) = __halves2bfloat162(l0, l1);
                }
            }
    } else {
        float* Cf = (float*)C0 + z * strC;
#pragma unroll
        for (int mt = 0; mt < 2; mt++)
#pragma unroll
            for (int nt = 0; nt < 8; nt++) {
                int col = cbase + nt * 8;
#pragma unroll
                for (int half = 0; half < 2; half++) {
                    int r = rbase + mt * 16 + half * 8;
                    float2 v;
                    v.x = acc[mt][nt][half * 2 + 0];
                    v.y = acc[mt][nt][half * 2 + 1];
                    *(float2*)(Cf + (size_t)r * ldC + col) = v;
                }
            }
    }
}

// ---------------- prep kernels ----------------------------------------------
__global__ void convert_split(const float* __restrict__ x,
                              __nv_bfloat16* __restrict__ h,
                              __nv_bfloat16* __restrict__ l, int n4)
{
    int i = blockIdx.x * blockDim.x + threadIdx.x;
    if (i >= n4) return;
    float4 v = ((const float4*)x)[i];
    __nv_bfloat16 h0 = __float2bfloat16(v.x), h1 = __float2bfloat16(v.y);
    __nv_bfloat16 h2 = __float2bfloat16(v.z), h3 = __float2bfloat16(v.w);
    ((__nv_bfloat162*)h)[i * 2]     = __halves2bfloat162(h0, h1);
    ((__nv_bfloat162*)h)[i * 2 + 1] = __halves2bfloat162(h2, h3);
    ((__nv_bfloat162*)l)[i * 2]     = __halves2bfloat162(
        __float2bfloat16(v.x - __bfloat162float(h0)),
        __float2bfloat16(v.y - __bfloat162float(h1)));
    ((__nv_bfloat162*)l)[i * 2 + 1] = __halves2bfloat162(
        __float2bfloat16(v.z - __bfloat162float(h2)),
        __float2bfloat16(v.w - __bfloat162float(h3)));
}

// W[d][e] fp32 -> Wt hi/lo [e][d] bf16 (768x768)
__global__ void transW(const float* __restrict__ W,
                       __nv_bfloat16* __restrict__ th,
                       __nv_bfloat16* __restrict__ tl)
{
    __shared__ float t[32][33];
    const int tx = threadIdx.x, ty = threadIdx.y;      // block (32, 8)
    const int d0 = blockIdx.y * 32, e0 = blockIdx.x * 32;
#pragma unroll
    for (int k = 0; k < 4; k++)
        t[ty + 8 * k][tx] = W[(size_t)(d0 + ty + 8 * k) * DD + e0 + tx];
    __syncthreads();
#pragma unroll
    for (int k = 0; k < 4; k++) {
        float v = t[tx][ty + 8 * k];
        __nv_bfloat16 h = __float2bfloat16(v);
        size_t o = (size_t)(e0 + ty + 8 * k) * DD + d0 + tx;
        th[o] = h;
        tl[o] = __float2bfloat16(v - __bfloat162float(h));
    }
}

// V hi/lo [b][l][d] -> Vt hi/lo [b][d][l]
__global__ void transV(const __nv_bfloat16* __restrict__ vh,
                       const __nv_bfloat16* __restrict__ vl,
                       __nv_bfloat16* __restrict__ oth,
                       __nv_bfloat16* __restrict__ otl)
{
    __shared__ __nv_bfloat16 th[32][33], tl[32][33];
    const int tx = threadIdx.x, ty = threadIdx.y;      // block (32, 8)
    const int d0 = blockIdx.x * 32, l0 = blockIdx.y * 32;
    const size_t zb = (size_t)blockIdx.z;
#pragma unroll
    for (int k = 0; k < 4; k++) {
        size_t o = (zb * LL + l0 + ty + 8 * k) * DD + d0 + tx;
        th[ty + 8 * k][tx] = vh[o];
        tl[ty + 8 * k][tx] = vl[o];
    }
    __syncthreads();
#pragma unroll
    for (int k = 0; k < 4; k++) {
        size_t o = (zb * DD + d0 + ty + 8 * k) * (size_t)LL + l0 + tx;
        oth[o] = th[tx][ty + 8 * k];
        otl[o] = tl[tx][ty + 8 * k];
    }
}

// ---------------- softmax: fp32 S row -> bf16 hi/lo P row -------------------
__global__ void __launch_bounds__(256)
softmax_split(const float* __restrict__ S,
              __nv_bfloat16* __restrict__ Ph, __nv_bfloat16* __restrict__ Pl)
{
    __shared__ float sh[LL];
    __shared__ float red[256];
    const float* p = S + (size_t)blockIdx.x * LL;
    const int tid = threadIdx.x;

    float m = -3.402823466e38f;
#pragma unroll
    for (int i = 0; i < LL / (256 * 4); i++) {
        int idx = (i * 256 + tid) * 4;
        float4 v = *(const float4*)(p + idx);
        *(float4*)&sh[idx] = v;
        m = fmaxf(m, fmaxf(fmaxf(v.x, v.y), fmaxf(v.z, v.w)));
    }
    red[tid] = m;
    __syncthreads();
#pragma unroll
    for (int s = 128; s > 0; s >>= 1) {
        if (tid < s) red[tid] = fmaxf(red[tid], red[tid + s]);
        __syncthreads();
    }
    m = red[0];
    __syncthreads();

    float sum = 0.0f;
#pragma unroll
    for (int i = 0; i < LL / (256 * 4); i++) {
        int idx = (i * 256 + tid) * 4;
        float4 v = *(float4*)&sh[idx];
        v.x = __expf(v.x - m); v.y = __expf(v.y - m);
        v.z = __expf(v.z - m); v.w = __expf(v.w - m);
        *(float4*)&sh[idx] = v;
        sum += v.x + v.y + v.z + v.w;
    }
    red[tid] = sum;
    __syncthreads();
#pragma unroll
    for (int s = 128; s > 0; s >>= 1) {
        if (tid < s) red[tid] += red[tid + s];
        __syncthreads();
    }
    const float inv = 1.0f / red[0];
    __syncthreads();

    __nv_bfloat162* ph = (__nv_bfloat162*)(Ph + (size_t)blockIdx.x * LL);
    __nv_bfloat162* pl = (__nv_bfloat162*)(Pl + (size_t)blockIdx.x * LL);
#pragma unroll
    for (int i = 0; i < LL / (256 * 4); i++) {
        int idx = (i * 256 + tid) * 4;
        float4 v = *(float4*)&sh[idx];
        v.x *= inv; v.y *= inv; v.z *= inv; v.w *= inv;
        __nv_bfloat16 h0 = __float2bfloat16(v.x), h1 = __float2bfloat16(v.y);
        __nv_bfloat16 h2 = __float2bfloat16(v.z), h3 = __float2bfloat16(v.w);
        ph[idx / 2]     = __halves2bfloat162(h0, h1);
        ph[idx / 2 + 1] = __halves2bfloat162(h2, h3);
        pl[idx / 2]     = __halves2bfloat162(
            __float2bfloat16(v.x - __bfloat162float(h0)),
            __float2bfloat16(v.y - __bfloat162float(h1)));
        pl[idx / 2 + 1] = __halves2bfloat162(
            __float2bfloat16(v.z - __bfloat162float(h2)),
            __float2bfloat16(v.w - __bfloat162float(h3)));
    }
}

// ---------------- orchestration ---------------------------------------------
extern "C" void kernel_launch(void* const* d_in, const int* in_sizes, int n_in,
                              void* d_out, int out_size)
{
    const float* X  = (const float*)d_in[0];
    const float* Wq = (const float*)d_in[1];
    const float* bq = (const float*)d_in[2];
    const float* Wk = (const float*)d_in[3];
    const float* bk = (const float*)d_in[4];
    const float* Wv = (const float*)d_in[5];
    const float* bv = (const float*)d_in[6];
    float* out = (float*)d_out;

    __nv_bfloat16 *Xh, *Xl, *Wth, *Wtl, *Qh, *Ql, *Kh, *Kl, *Vh, *Vl, *Vth, *Vtl, *Ph, *Pl;
    float* S;
    cudaGetSymbolAddress((void**)&Xh, g_Xh);   cudaGetSymbolAddress((void**)&Xl, g_Xl);
    cudaGetSymbolAddress((void**)&Wth, g_Wth); cudaGetSymbolAddress((void**)&Wtl, g_Wtl);
    cudaGetSymbolAddress((void**)&Qh, g_Qh);   cudaGetSymbolAddress((void**)&Ql, g_Ql);
    cudaGetSymbolAddress((void**)&Kh, g_Kh);   cudaGetSymbolAddress((void**)&Kl, g_Kl);
    cudaGetSymbolAddress((void**)&Vh, g_Vh);   cudaGetSymbolAddress((void**)&Vl, g_Vl);
    cudaGetSymbolAddress((void**)&Vth, g_Vth); cudaGetSymbolAddress((void**)&Vtl, g_Vtl);
    cudaGetSymbolAddress((void**)&Ph, g_Ph);   cudaGetSymbolAddress((void**)&Pl, g_Pl);
    cudaGetSymbolAddress((void**)&S, g_S);

    cudaFuncSetAttribute(gemm_mma<0>, cudaFuncAttributeMaxDynamicSharedMemorySize, SMEM_BYTES);
    cudaFuncSetAttribute(gemm_mma<2>, cudaFuncAttributeMaxDynamicSharedMemorySize, SMEM_BYTES);

    // 1) split X into bf16 hi/lo
    {
        int n4 = ML * DD / 4;
        convert_split<<<(n4 + 255) / 256, 256>>>(X, Xh, Xl, n4);
    }
    // 2) transpose+split weights
    {
        dim3 g(DD / 32, DD / 32), b(32, 8);
        transW<<<g, b>>>(Wq, Wth + 0 * (size_t)DD * DD, Wtl + 0 * (size_t)DD * DD);
        transW<<<g, b>>>(Wk, Wth + 1 * (size_t)DD * DD, Wtl + 1 * (size_t)DD * DD);
        transW<<<g, b>>>(Wv, Wth + 2 * (size_t)DD * DD, Wtl + 2 * (size_t)DD * DD);
    }
    // 3) projections -> bf16 hi/lo + bias
    {
        dim3 g(DD / 128, ML / 128, 1);
        gemm_mma<0><<<g, 256, SMEM_BYTES>>>(Xh, Xl, Wth + 0 * (size_t)DD * DD,
            Wtl + 0 * (size_t)DD * DD, bq, Qh, Ql, DD, DD, 0, 0, 0);
        gemm_mma<0><<<g, 256, SMEM_BYTES>>>(Xh, Xl, Wth + 1 * (size_t)DD * DD,
            Wtl + 1 * (size_t)DD * DD, bk, Kh, Kl, DD, DD, 0, 0, 0);
        gemm_mma<0><<<g, 256, SMEM_BYTES>>>(Xh, Xl, Wth + 2 * (size_t)DD * DD,
            Wtl + 2 * (size_t)DD * DD, bv, Vh, Vl, DD, DD, 0, 0, 0);
    }
    // 4) transpose V hi/lo per batch -> [b][d][l]
    {
        dim3 g(DD / 32, LL / 32, BB), b(32, 8);
        transV<<<g, b>>>(Vh, Vl, Vth, Vtl);
    }
    // 5) logits: S[b] = Q[b] @ K[b]^T (fp32 out)
    {
        dim3 g(LL / 128, LL / 128, BB);
        gemm_mma<2><<<g, 256, SMEM_BYTES>>>(Qh, Ql, Kh, Kl, nullptr, S, nullptr,
            DD, LL, (long long)LL * DD, (long long)LL * DD, (long long)LL * LL);
    }
    // 6) softmax rows -> bf16 hi/lo P
    softmax_split<<<ML, 256>>>(S, Ph, Pl);
    // 7) output: O[b] = P[b] @ Vt[b]^T (fp32 out)
    {
        dim3 g(DD / 128, LL / 128, BB);
        gemm_mma<2><<<g, 256, SMEM_BYTES>>>(Ph, Pl, Vth, Vtl, nullptr, out, nullptr,
            LL, DD, (long long)LL * LL, (long long)DD * LL, (long long)LL * DD);
    }
}

// round 4
// speedup vs baseline: 3.2944x; 1.0191x over previous
#include <cuda_runtime.h>
#include <cuda_bf16.h>
#include <cstdint>

#define BB 4
#define LL 4096
#define DD 768
#define ML (BB*LL)

// ---------------- scratch (__device__ globals; allocation-free contract) ----
__device__ __nv_bfloat16 g_Xh[(size_t)ML * DD], g_Xl[(size_t)ML * DD];
__device__ __nv_bfloat16 g_Wth[3][(size_t)DD * DD], g_Wtl[3][(size_t)DD * DD];
__device__ __nv_bfloat16 g_Qh[(size_t)ML * DD], g_Ql[(size_t)ML * DD];
__device__ __nv_bfloat16 g_Kh[(size_t)ML * DD], g_Kl[(size_t)ML * DD];
__device__ __nv_bfloat16 g_Vh[(size_t)ML * DD], g_Vl[(size_t)ML * DD];
__device__ __nv_bfloat16 g_Vth[(size_t)ML * DD], g_Vtl[(size_t)ML * DD];
__device__ float         g_S [(size_t)BB * LL * LL];
__device__ __nv_bfloat16 g_Ph[(size_t)BB * LL * LL], g_Pl[(size_t)BB * LL * LL];

// ---------------- helpers (base-family ISA only) -----------------------------
__device__ __forceinline__ uint32_t s2u(const void* p) {
    uint32_t a;
    asm("{ .reg .u64 t; cvta.to.shared.u64 t, %1; cvt.u32.u64 %0, t; }"
        : "=r"(a) : "l"(p));
    return a;
}
__device__ __forceinline__ uint32_t sw128(uint32_t off) {
    return off ^ ((off >> 3) & 0x70);
}
__device__ __forceinline__ void cp16(uint32_t saddr, const void* g) {
    asm volatile("cp.async.cg.shared.global [%0], [%1], 16;" :: "r"(saddr), "l"(g));
}
__device__ __forceinline__ void cp_commit() {
    asm volatile("cp.async.commit_group;");
}
template <int N>
__device__ __forceinline__ void cp_wait() {
    asm volatile("cp.async.wait_group %0;" :: "n"(N));
}
__device__ __forceinline__ void ldm_x4(uint32_t* r, uint32_t addr) {
    asm volatile("ldmatrix.sync.aligned.m8n8.x4.shared.b16 {%0,%1,%2,%3}, [%4];"
                 : "=r"(r[0]), "=r"(r[1]), "=r"(r[2]), "=r"(r[3]) : "r"(addr));
}
__device__ __forceinline__ void mma_bf16(float* c, const uint32_t* a, const uint32_t* b) {
    asm volatile(
        "mma.sync.aligned.m16n8k16.row.col.f32.bf16.bf16.f32 "
        "{%0,%1,%2,%3}, {%4,%5,%6,%7}, {%8,%9}, {%0,%1,%2,%3};"
        : "+f"(c[0]), "+f"(c[1]), "+f"(c[2]), "+f"(c[3])
        : "r"(a[0]), "r"(a[1]), "r"(a[2]), "r"(a[3]), "r"(b[0]), "r"(b[1]));
}

// ---------------- bf16x3 HMMA GEMM ------------------------------------------
// C[M,N] = sum_k A[m,k]*B[n,k]; A,B K-major bf16 hi/lo, row stride K.
// 128x128 CTA tile, 64-k chunks, 3-stage cp.async pipeline (1 sync/chunk).
// EPI=0: +bias (per-z pointers), write bf16 hi/lo. EPI=2: fp32 out (+z*strC).
static constexpr int STAGE_BYTES = 65536;               // Ah,Al,Bh,Bl x 16KB
static constexpr int SMEM_BYTES  = 3 * STAGE_BYTES;     // 192 KB

struct EpiPtrs { const float* bias; __nv_bfloat16* ch; __nv_bfloat16* cl; };
struct EpiPtrs3 { EpiPtrs p[3]; };

__device__ __forceinline__ void load_tile64(const __nv_bfloat16* __restrict__ g,
                                            long long ld, uint32_t sdst, int tid) {
#pragma unroll
    for (int it = 0; it < 4; it++) {
        int u = it * 256 + tid;            // 128 rows x 8 16B-segments
        int row = u >> 3, seg = u & 7;
        cp16(sdst + sw128(row * 128 + seg * 16), g + (long long)row * ld + seg * 8);
    }
}

template <int EPI>
__global__ void __launch_bounds__(256, 1)
gemm_mma(const __nv_bfloat16* __restrict__ Ah, const __nv_bfloat16* __restrict__ Al,
         const __nv_bfloat16* __restrict__ Bh, const __nv_bfloat16* __restrict__ Bl,
         EpiPtrs3 EP, void* __restrict__ C0,
         int K, int ldC,
         long long strA, long long strB, long long strC)
{
    extern __shared__ char smem[];
    const uint32_t sbase = s2u(smem);
    const int tid  = threadIdx.x;
    const int lane = tid & 31;
    const int warp = tid >> 5;
    const int wm = warp >> 1;   // 0..3
    const int wn = warp & 1;    // 0..1
    const int m0 = blockIdx.y * 128, n0 = blockIdx.x * 128;
    const long long z = blockIdx.z;

    const __nv_bfloat16* aH = Ah + z * strA + (long long)m0 * K;
    const __nv_bfloat16* aL = Al + z * strA + (long long)m0 * K;
    const __nv_bfloat16* bH = Bh + z * strB + (long long)n0 * K;
    const __nv_bfloat16* bL = Bl + z * strB + (long long)n0 * K;

    float acc[2][8][4];
#pragma unroll
    for (int mt = 0; mt < 2; mt++)
#pragma unroll
        for (int nt = 0; nt < 8; nt++)
#pragma unroll
            for (int i = 0; i < 4; i++) acc[mt][nt][i] = 0.0f;

    const int nch = K >> 6;    // always >= 2 here

    // prologue: chunks 0 and 1
#pragma unroll
    for (int c = 0; c < 2; c++) {
        uint32_t sb = sbase + c * STAGE_BYTES;
        load_tile64(aH + c * 64, K, sb,         tid);
        load_tile64(aL + c * 64, K, sb + 16384, tid);
        load_tile64(bH + c * 64, K, sb + 32768, tid);
        load_tile64(bL + c * 64, K, sb + 49152, tid);
        cp_commit();
    }

    int st_next = 2;   // stage index for chunk c+2
    for (int c = 0; c < nch; c++) {
        cp_wait<1>();          // chunk c resident
        __syncthreads();       // all warps done with chunk c-1 -> stage st_next free

        if (c + 2 < nch) {
            uint32_t sb = sbase + st_next * STAGE_BYTES;
            load_tile64(aH + (c + 2) * 64, K, sb,         tid);
            load_tile64(aL + (c + 2) * 64, K, sb + 16384, tid);
            load_tile64(bH + (c + 2) * 64, K, sb + 32768, tid);
            load_tile64(bL + (c + 2) * 64, K, sb + 49152, tid);
        }
        cp_commit();           // one group per iteration (possibly empty)
        st_next = (st_next == 2) ? 0 : st_next + 1;

        const uint32_t sb  = sbase + (c % 3) * STAGE_BYTES;
        const uint32_t sAh = sb, sAl = sb + 16384, sBh = sb + 32768, sBl = sb + 49152;

#pragma unroll
        for (int ks = 0; ks < 4; ks++) {
            uint32_t ah[2][4], al[2][4];
#pragma unroll
            for (int mt = 0; mt < 2; mt++) {
                uint32_t off = sw128((uint32_t)((wm * 32 + mt * 16 + (lane & 15)) * 128
                                                + (ks * 2 + (lane >> 4)) * 16));
                ldm_x4(ah[mt], sAh + off);
                ldm_x4(al[mt], sAl + off);
            }
            const int g = lane >> 3;
#pragma unroll
            for (int np = 0; np < 4; np++) {
                // x4 covers n=16 (np pair) x k=16: lanes 0-7 rows n..n+7 klo,
                // 8-15 same rows khi, 16-23 rows n+8..n+15 klo, 24-31 khi
                uint32_t boff = sw128((uint32_t)(
                    (wn * 64 + np * 16 + ((g >> 1) << 3) + (lane & 7)) * 128
                    + ks * 32 + (g & 1) * 16));
                uint32_t bh[4], bl[4];
                ldm_x4(bh, sBh + boff);
                ldm_x4(bl, sBl + boff);
#pragma unroll
                for (int mt = 0; mt < 2; mt++) {
                    mma_bf16(acc[mt][np * 2 + 0], ah[mt], bh + 0);
                    mma_bf16(acc[mt][np * 2 + 1], ah[mt], bh + 2);
                    mma_bf16(acc[mt][np * 2 + 0], ah[mt], bl + 0);
                    mma_bf16(acc[mt][np * 2 + 1], ah[mt], bl + 2);
                    mma_bf16(acc[mt][np * 2 + 0], al[mt], bh + 0);
                    mma_bf16(acc[mt][np * 2 + 1], al[mt], bh + 2);
                }
            }
        }
    }

    // ----- epilogue -----
    const int rbase = m0 + wm * 32 + (lane >> 2);
    const int cbase = n0 + wn * 64 + 2 * (lane & 3);
    if (EPI == 0) {
        const EpiPtrs e = EP.p[z];
#pragma unroll
        for (int mt = 0; mt < 2; mt++)
#pragma unroll
            for (int nt = 0; nt < 8; nt++) {
                int col = cbase + nt * 8;
                float b0 = e.bias[col], b1 = e.bias[col + 1];
#pragma unroll
                for (int half = 0; half < 2; half++) {
                    int r = rbase + mt * 16 + half * 8;
                    float v0 = acc[mt][nt][half * 2 + 0] + b0;
                    float v1 = acc[mt][nt][half * 2 + 1] + b1;
                    __nv_bfloat16 h0 = __float2bfloat16(v0);
                    __nv_bfloat16 h1 = __float2bfloat16(v1);
                    __nv_bfloat16 l0 = __float2bfloat16(v0 - __bfloat162float(h0));
                    __nv_bfloat16 l1 = __float2bfloat16(v1 - __bfloat162float(h1));
                    *(__nv_bfloat162*)(e.ch + (size_t)r * ldC + col) = __halves2bfloat162(h0, h1);
                    *(__nv_bfloat162*)(e.cl + (size_t)r * ldC + col) = __halves2bfloat162(l0, l1);
                }
            }
    } else {
        float* Cf = (float*)C0 + z * strC;
#pragma unroll
        for (int mt = 0; mt < 2; mt++)
#pragma unroll
            for (int nt = 0; nt < 8; nt++) {
                int col = cbase + nt * 8;
#pragma unroll
                for (int half = 0; half < 2; half++) {
                    int r = rbase + mt * 16 + half * 8;
                    float2 v;
                    v.x = acc[mt][nt][half * 2 + 0];
                    v.y = acc[mt][nt][half * 2 + 1];
                    *(float2*)(Cf + (size_t)r * ldC + col) = v;
                }
            }
    }
}

// ---------------- prep kernels ----------------------------------------------
__global__ void convert_split(const float* __restrict__ x,
                              __nv_bfloat16* __restrict__ h,
                              __nv_bfloat16* __restrict__ l, int n4)
{
    int i = blockIdx.x * blockDim.x + threadIdx.x;
    if (i >= n4) return;
    float4 v = ((const float4*)x)[i];
    __nv_bfloat16 h0 = __float2bfloat16(v.x), h1 = __float2bfloat16(v.y);
    __nv_bfloat16 h2 = __float2bfloat16(v.z), h3 = __float2bfloat16(v.w);
    ((__nv_bfloat162*)h)[i * 2]     = __halves2bfloat162(h0, h1);
    ((__nv_bfloat162*)h)[i * 2 + 1] = __halves2bfloat162(h2, h3);
    ((__nv_bfloat162*)l)[i * 2]     = __halves2bfloat162(
        __float2bfloat16(v.x - __bfloat162float(h0)),
        __float2bfloat16(v.y - __bfloat162float(h1)));
    ((__nv_bfloat162*)l)[i * 2 + 1] = __halves2bfloat162(
        __float2bfloat16(v.z - __bfloat162float(h2)),
        __float2bfloat16(v.w - __bfloat162float(h3)));
}

// W[d][e] fp32 -> Wt hi/lo [e][d] bf16 (768x768), 3 weights via blockIdx.z
__global__ void transW3(const float* __restrict__ W0, const float* __restrict__ W1,
                        const float* __restrict__ W2,
                        __nv_bfloat16* __restrict__ th, __nv_bfloat16* __restrict__ tl)
{
    __shared__ float t[32][33];
    const int tx = threadIdx.x, ty = threadIdx.y;      // block (32, 8)
    const int d0 = blockIdx.y * 32, e0 = blockIdx.x * 32;
    const float* W = (blockIdx.z == 0) ? W0 : (blockIdx.z == 1) ? W1 : W2;
    th += (size_t)blockIdx.z * DD * DD;
    tl += (size_t)blockIdx.z * DD * DD;
#pragma unroll
    for (int k = 0; k < 4; k++)
        t[ty + 8 * k][tx] = W[(size_t)(d0 + ty + 8 * k) * DD + e0 + tx];
    __syncthreads();
#pragma unroll
    for (int k = 0; k < 4; k++) {
        float v = t[tx][ty + 8 * k];
        __nv_bfloat16 h = __float2bfloat16(v);
        size_t o = (size_t)(e0 + ty + 8 * k) * DD + d0 + tx;
        th[o] = h;
        tl[o] = __float2bfloat16(v - __bfloat162float(h));
    }
}

// V hi/lo [b][l][d] -> Vt hi/lo [b][d][l]
__global__ void transV(const __nv_bfloat16* __restrict__ vh,
                       const __nv_bfloat16* __restrict__ vl,
                       __nv_bfloat16* __restrict__ oth,
                       __nv_bfloat16* __restrict__ otl)
{
    __shared__ __nv_bfloat16 th[32][33], tl[32][33];
    const int tx = threadIdx.x, ty = threadIdx.y;      // block (32, 8)
    const int d0 = blockIdx.x * 32, l0 = blockIdx.y * 32;
    const size_t zb = (size_t)blockIdx.z;
#pragma unroll
    for (int k = 0; k < 4; k++) {
        size_t o = (zb * LL + l0 + ty + 8 * k) * DD + d0 + tx;
        th[ty + 8 * k][tx] = vh[o];
        tl[ty + 8 * k][tx] = vl[o];
    }
    __syncthreads();
#pragma unroll
    for (int k = 0; k < 4; k++) {
        size_t o = (zb * DD + d0 + ty + 8 * k) * (size_t)LL + l0 + tx;
        oth[o] = th[tx][ty + 8 * k];
        otl[o] = tl[tx][ty + 8 * k];
    }
}

// ---------------- softmax: fp32 S row -> bf16 hi/lo P row -------------------
__global__ void __launch_bounds__(256)
softmax_split(const float* __restrict__ S,
              __nv_bfloat16* __restrict__ Ph, __nv_bfloat16* __restrict__ Pl)
{
    __shared__ float sh[LL];
    __shared__ float red[256];
    const float* p = S + (size_t)blockIdx.x * LL;
    const int tid = threadIdx.x;

    float m = -3.402823466e38f;
#pragma unroll
    for (int i = 0; i < LL / (256 * 4); i++) {
        int idx = (i * 256 + tid) * 4;
        float4 v = *(const float4*)(p + idx);
        *(float4*)&sh[idx] = v;
        m = fmaxf(m, fmaxf(fmaxf(v.x, v.y), fmaxf(v.z, v.w)));
    }
    red[tid] = m;
    __syncthreads();
#pragma unroll
    for (int s = 128; s > 0; s >>= 1) {
        if (tid < s) red[tid] = fmaxf(red[tid], red[tid + s]);
        __syncthreads();
    }
    m = red[0];
    __syncthreads();

    float sum = 0.0f;
#pragma unroll
    for (int i = 0; i < LL / (256 * 4); i++) {
        int idx = (i * 256 + tid) * 4;
        float4 v = *(float4*)&sh[idx];
        v.x = __expf(v.x - m); v.y = __expf(v.y - m);
        v.z = __expf(v.z - m); v.w = __expf(v.w - m);
        *(float4*)&sh[idx] = v;
        sum += v.x + v.y + v.z + v.w;
    }
    red[tid] = sum;
    __syncthreads();
#pragma unroll
    for (int s = 128; s > 0; s >>= 1) {
        if (tid < s) red[tid] += red[tid + s];
        __syncthreads();
    }
    const float inv = 1.0f / red[0];
    __syncthreads();

    __nv_bfloat162* ph = (__nv_bfloat162*)(Ph + (size_t)blockIdx.x * LL);
    __nv_bfloat162* pl = (__nv_bfloat162*)(Pl + (size_t)blockIdx.x * LL);
#pragma unroll
    for (int i = 0; i < LL / (256 * 4); i++) {
        int idx = (i * 256 + tid) * 4;
        float4 v = *(float4*)&sh[idx];
        v.x *= inv; v.y *= inv; v.z *= inv; v.w *= inv;
        __nv_bfloat16 h0 = __float2bfloat16(v.x), h1 = __float2bfloat16(v.y);
        __nv_bfloat16 h2 = __float2bfloat16(v.z), h3 = __float2bfloat16(v.w);
        ph[idx / 2]     = __halves2bfloat162(h0, h1);
        ph[idx / 2 + 1] = __halves2bfloat162(h2, h3);
        pl[idx / 2]     = __halves2bfloat162(
            __float2bfloat16(v.x - __bfloat162float(h0)),
            __float2bfloat16(v.y - __bfloat162float(h1)));
        pl[idx / 2 + 1] = __halves2bfloat162(
            __float2bfloat16(v.z - __bfloat162float(h2)),
            __float2bfloat16(v.w - __bfloat162float(h3)));
    }
}

// ---------------- orchestration ---------------------------------------------
extern "C" void kernel_launch(void* const* d_in, const int* in_sizes, int n_in,
                              void* d_out, int out_size)
{
    const float* X  = (const float*)d_in[0];
    const float* Wq = (const float*)d_in[1];
    const float* bq = (const float*)d_in[2];
    const float* Wk = (const float*)d_in[3];
    const float* bk = (const float*)d_in[4];
    const float* Wv = (const float*)d_in[5];
    const float* bv = (const float*)d_in[6];
    float* out = (float*)d_out;

    __nv_bfloat16 *Xh, *Xl, *Wth, *Wtl, *Qh, *Ql, *Kh, *Kl, *Vh, *Vl, *Vth, *Vtl, *Ph, *Pl;
    float* S;
    cudaGetSymbolAddress((void**)&Xh, g_Xh);   cudaGetSymbolAddress((void**)&Xl, g_Xl);
    cudaGetSymbolAddress((void**)&Wth, g_Wth); cudaGetSymbolAddress((void**)&Wtl, g_Wtl);
    cudaGetSymbolAddress((void**)&Qh, g_Qh);   cudaGetSymbolAddress((void**)&Ql, g_Ql);
    cudaGetSymbolAddress((void**)&Kh, g_Kh);   cudaGetSymbolAddress((void**)&Kl, g_Kl);
    cudaGetSymbolAddress((void**)&Vh, g_Vh);   cudaGetSymbolAddress((void**)&Vl, g_Vl);
    cudaGetSymbolAddress((void**)&Vth, g_Vth); cudaGetSymbolAddress((void**)&Vtl, g_Vtl);
    cudaGetSymbolAddress((void**)&Ph, g_Ph);   cudaGetSymbolAddress((void**)&Pl, g_Pl);
    cudaGetSymbolAddress((void**)&S, g_S);

    cudaFuncSetAttribute(gemm_mma<0>, cudaFuncAttributeMaxDynamicSharedMemorySize, SMEM_BYTES);
    cudaFuncSetAttribute(gemm_mma<2>, cudaFuncAttributeMaxDynamicSharedMemorySize, SMEM_BYTES);

    EpiPtrs3 none{};

    // 1) split X into bf16 hi/lo
    {
        int n4 = ML * DD / 4;
        convert_split<<<(n4 + 255) / 256, 256>>>(X, Xh, Xl, n4);
    }
    // 2) transpose+split weights (one launch, z = q/k/v)
    {
        dim3 g(DD / 32, DD / 32, 3), b(32, 8);
        transW3<<<g, b>>>(Wq, Wk, Wv, Wth, Wtl);
    }
    // 3) projections, one launch (z selects weight/bias/output)
    {
        EpiPtrs3 ep;
        ep.p[0] = {bq, Qh, Ql};
        ep.p[1] = {bk, Kh, Kl};
        ep.p[2] = {bv, Vh, Vl};
        dim3 g(DD / 128, ML / 128, 3);
        gemm_mma<0><<<g, 256, SMEM_BYTES>>>(Xh, Xl, Wth, Wtl, ep, nullptr,
            DD, DD, 0, (long long)DD * DD, 0);
    }
    // 4) transpose V hi/lo per batch -> [b][d][l]
    {
        dim3 g(DD / 32, LL / 32, BB), b(32, 8);
        transV<<<g, b>>>(Vh, Vl, Vth, Vtl);
    }
    // 5) logits: S[b] = Q[b] @ K[b]^T (fp32 out)
    {
        dim3 g(LL / 128, LL / 128, BB);
        gemm_mma<2><<<g, 256, SMEM_BYTES>>>(Qh, Ql, Kh, Kl, none, S,
            DD, LL, (long long)LL * DD, (long long)LL * DD, (long long)LL * LL);
    }
    // 6) softmax rows -> bf16 hi/lo P
    softmax_split<<<ML, 256>>>(S, Ph, Pl);
    // 7) output: O[b] = P[b] @ Vt[b]^T (fp32 out)
    {
        dim3 g(DD / 128, LL / 128, BB);
        gemm_mma<2><<<g, 256, SMEM_BYTES>>>(Ph, Pl, Vth, Vtl, none, out,
            LL, DD, (long long)LL * LL, (long long)DD * LL, (long long)LL * DD);
    }
}

// round 5
// speedup vs baseline: 3.5232x; 1.0695x over previous
#include <cuda_runtime.h>
#include <cuda_bf16.h>
#include <cstdint>

#define BB 4
#define LL 4096
#define DD 768
#define ML (BB*LL)

// ---------------- scratch (__device__ globals; allocation-free contract) ----
__device__ __nv_bfloat16 g_Xh[(size_t)ML * DD], g_Xl[(size_t)ML * DD];
__device__ __nv_bfloat16 g_Wth[3][(size_t)DD * DD], g_Wtl[3][(size_t)DD * DD];
__device__ __nv_bfloat16 g_Qh[(size_t)ML * DD], g_Ql[(size_t)ML * DD];
__device__ __nv_bfloat16 g_Kh[(size_t)ML * DD], g_Kl[(size_t)ML * DD];
__device__ __nv_bfloat16 g_Vh[(size_t)ML * DD], g_Vl[(size_t)ML * DD];
__device__ __nv_bfloat16 g_Vth[(size_t)ML * DD], g_Vtl[(size_t)ML * DD];
__device__ float         g_S [(size_t)BB * LL * LL];
__device__ __nv_bfloat16 g_Ph[(size_t)BB * LL * LL], g_Pl[(size_t)BB * LL * LL];

// ---------------- helpers (base-family ISA only) -----------------------------
__device__ __forceinline__ uint32_t s2u(const void* p) {
    uint32_t a;
    asm("{ .reg .u64 t; cvta.to.shared.u64 t, %1; cvt.u32.u64 %0, t; }"
        : "=r"(a) : "l"(p));
    return a;
}
__device__ __forceinline__ uint32_t sw128(uint32_t off) {
    return off ^ ((off >> 3) & 0x70);
}
__device__ __forceinline__ void cp16(uint32_t saddr, const void* g) {
    asm volatile("cp.async.cg.shared.global [%0], [%1], 16;" :: "r"(saddr), "l"(g));
}
__device__ __forceinline__ void cp_commit() {
    asm volatile("cp.async.commit_group;");
}
template <int N>
__device__ __forceinline__ void cp_wait() {
    asm volatile("cp.async.wait_group %0;" :: "n"(N));
}
__device__ __forceinline__ void ldm_x4(uint32_t* r, uint32_t addr) {
    asm volatile("ldmatrix.sync.aligned.m8n8.x4.shared.b16 {%0,%1,%2,%3}, [%4];"
                 : "=r"(r[0]), "=r"(r[1]), "=r"(r[2]), "=r"(r[3]) : "r"(addr));
}
__device__ __forceinline__ void mma_bf16(float* c, const uint32_t* a, const uint32_t* b) {
    asm volatile(
        "mma.sync.aligned.m16n8k16.row.col.f32.bf16.bf16.f32 "
        "{%0,%1,%2,%3}, {%4,%5,%6,%7}, {%8,%9}, {%0,%1,%2,%3};"
        : "+f"(c[0]), "+f"(c[1]), "+f"(c[2]), "+f"(c[3])
        : "r"(a[0]), "r"(a[1]), "r"(a[2]), "r"(a[3]), "r"(b[0]), "r"(b[1]));
}

// ---------------- bf16x3 HMMA GEMM ------------------------------------------
// C[M,N] = sum_k A[m,k]*B[n,k]; A,B K-major bf16 hi/lo, row stride K.
// 256x128 CTA tile (8 warps, 64x64 per warp), 64-k chunks, 2-stage pipeline.
// EPI=0: +bias (per-z ptrs), bf16 hi/lo out. EPI=2: fp32 out (+z*strC).
static constexpr int A_BYTES = 256 * 128;                 // 32 KB per (h|l)
static constexpr int B_BYTES = 128 * 128;                 // 16 KB per (h|l)
static constexpr int STAGE_BYTES = 2 * A_BYTES + 2 * B_BYTES;   // 96 KB
static constexpr int SMEM_BYTES  = 2 * STAGE_BYTES;             // 192 KB
// stage offsets
#define OFF_AH 0
#define OFF_AL (A_BYTES)
#define OFF_BH (2*A_BYTES)
#define OFF_BL (2*A_BYTES + B_BYTES)

struct EpiPtrs { const float* bias; __nv_bfloat16* ch; __nv_bfloat16* cl; };
struct EpiPtrs3 { EpiPtrs p[3]; };

template <int ROWS>
__device__ __forceinline__ void load_tile(const __nv_bfloat16* __restrict__ g,
                                          long long ld, uint32_t sdst, int tid) {
#pragma unroll
    for (int it = 0; it < ROWS * 8 / 256; it++) {
        int u = it * 256 + tid;            // ROWS rows x 8 16B-segments
        int row = u >> 3, seg = u & 7;
        cp16(sdst + sw128(row * 128 + seg * 16), g + (long long)row * ld + seg * 8);
    }
}

template <int EPI>
__global__ void __launch_bounds__(256, 1)
gemm_mma(const __nv_bfloat16* __restrict__ Ah, const __nv_bfloat16* __restrict__ Al,
         const __nv_bfloat16* __restrict__ Bh, const __nv_bfloat16* __restrict__ Bl,
         EpiPtrs3 EP, void* __restrict__ C0,
         int K, int ldC,
         long long strA, long long strB, long long strC)
{
    extern __shared__ char smem[];
    const uint32_t sbase = s2u(smem);
    const int tid  = threadIdx.x;
    const int lane = tid & 31;
    const int warp = tid >> 5;
    const int wm = warp >> 1;   // 0..3  (64-row slice)
    const int wn = warp & 1;    // 0..1  (64-col slice)
    const int m0 = blockIdx.y * 256, n0 = blockIdx.x * 128;
    const long long z = blockIdx.z;

    const __nv_bfloat16* aH = Ah + z * strA + (long long)m0 * K;
    const __nv_bfloat16* aL = Al + z * strA + (long long)m0 * K;
    const __nv_bfloat16* bH = Bh + z * strB + (long long)n0 * K;
    const __nv_bfloat16* bL = Bl + z * strB + (long long)n0 * K;

    float acc[4][8][4];
#pragma unroll
    for (int mt = 0; mt < 4; mt++)
#pragma unroll
        for (int nt = 0; nt < 8; nt++)
#pragma unroll
            for (int i = 0; i < 4; i++) acc[mt][nt][i] = 0.0f;

    const int nch = K >> 6;

    // prologue: chunk 0
    {
        load_tile<256>(aH, K, sbase + OFF_AH, tid);
        load_tile<256>(aL, K, sbase + OFF_AL, tid);
        load_tile<128>(bH, K, sbase + OFF_BH, tid);
        load_tile<128>(bL, K, sbase + OFF_BL, tid);
        cp_commit();
    }

    for (int c = 0; c < nch; c++) {
        cp_wait<0>();          // chunk c resident
        __syncthreads();       // everyone done with chunk c-1 -> other stage free

        if (c + 1 < nch) {
            uint32_t sb = sbase + ((c + 1) & 1) * STAGE_BYTES;
            load_tile<256>(aH + (c + 1) * 64, K, sb + OFF_AH, tid);
            load_tile<256>(aL + (c + 1) * 64, K, sb + OFF_AL, tid);
            load_tile<128>(bH + (c + 1) * 64, K, sb + OFF_BH, tid);
            load_tile<128>(bL + (c + 1) * 64, K, sb + OFF_BL, tid);
            cp_commit();
        }

        const uint32_t sb  = sbase + (c & 1) * STAGE_BYTES;
        const uint32_t sAh = sb + OFF_AH, sAl = sb + OFF_AL;
        const uint32_t sBh = sb + OFF_BH, sBl = sb + OFF_BL;

#pragma unroll
        for (int ks = 0; ks < 4; ks++) {
            uint32_t ah[4][4], al[4][4];
#pragma unroll
            for (int mt = 0; mt < 4; mt++) {
                uint32_t off = sw128((uint32_t)((wm * 64 + mt * 16 + (lane & 15)) * 128
                                                + (ks * 2 + (lane >> 4)) * 16));
                ldm_x4(ah[mt], sAh + off);
                ldm_x4(al[mt], sAl + off);
            }
            const int g = lane >> 3;
#pragma unroll
            for (int np = 0; np < 4; np++) {
                uint32_t boff = sw128((uint32_t)(
                    (wn * 64 + np * 16 + ((g >> 1) << 3) + (lane & 7)) * 128
                    + ks * 32 + (g & 1) * 16));
                uint32_t bh[4], bl[4];
                ldm_x4(bh, sBh + boff);
                ldm_x4(bl, sBl + boff);
#pragma unroll
                for (int mt = 0; mt < 4; mt++) {
                    mma_bf16(acc[mt][np * 2 + 0], ah[mt], bh + 0);
                    mma_bf16(acc[mt][np * 2 + 1], ah[mt], bh + 2);
                    mma_bf16(acc[mt][np * 2 + 0], ah[mt], bl + 0);
                    mma_bf16(acc[mt][np * 2 + 1], ah[mt], bl + 2);
                    mma_bf16(acc[mt][np * 2 + 0], al[mt], bh + 0);
                    mma_bf16(acc[mt][np * 2 + 1], al[mt], bh + 2);
                }
            }
        }
    }

    // ----- epilogue -----
    const int rbase = m0 + wm * 64 + (lane >> 2);
    const int cbase = n0 + wn * 64 + 2 * (lane & 3);
    if (EPI == 0) {
        const EpiPtrs e = EP.p[z];
#pragma unroll
        for (int mt = 0; mt < 4; mt++)
#pragma unroll
            for (int nt = 0; nt < 8; nt++) {
                int col = cbase + nt * 8;
                float b0 = e.bias[col], b1 = e.bias[col + 1];
#pragma unroll
                for (int half = 0; half < 2; half++) {
                    int r = rbase + mt * 16 + half * 8;
                    float v0 = acc[mt][nt][half * 2 + 0] + b0;
                    float v1 = acc[mt][nt][half * 2 + 1] + b1;
                    __nv_bfloat16 h0 = __float2bfloat16(v0);
                    __nv_bfloat16 h1 = __float2bfloat16(v1);
                    __nv_bfloat16 l0 = __float2bfloat16(v0 - __bfloat162float(h0));
                    __nv_bfloat16 l1 = __float2bfloat16(v1 - __bfloat162float(h1));
                    *(__nv_bfloat162*)(e.ch + (size_t)r * ldC + col) = __halves2bfloat162(h0, h1);
                    *(__nv_bfloat162*)(e.cl + (size_t)r * ldC + col) = __halves2bfloat162(l0, l1);
                }
            }
    } else {
        float* Cf = (float*)C0 + z * strC;
#pragma unroll
        for (int mt = 0; mt < 4; mt++)
#pragma unroll
            for (int nt = 0; nt < 8; nt++) {
                int col = cbase + nt * 8;
#pragma unroll
                for (int half = 0; half < 2; half++) {
                    int r = rbase + mt * 16 + half * 8;
                    float2 v;
                    v.x = acc[mt][nt][half * 2 + 0];
                    v.y = acc[mt][nt][half * 2 + 1];
                    *(float2*)(Cf + (size_t)r * ldC + col) = v;
                }
            }
    }
}

// ---------------- prep kernels ----------------------------------------------
__global__ void convert_split(const float* __restrict__ x,
                              __nv_bfloat16* __restrict__ h,
                              __nv_bfloat16* __restrict__ l, int n4)
{
    int i = blockIdx.x * blockDim.x + threadIdx.x;
    if (i >= n4) return;
    float4 v = ((const float4*)x)[i];
    __nv_bfloat16 h0 = __float2bfloat16(v.x), h1 = __float2bfloat16(v.y);
    __nv_bfloat16 h2 = __float2bfloat16(v.z), h3 = __float2bfloat16(v.w);
    ((__nv_bfloat162*)h)[i * 2]     = __halves2bfloat162(h0, h1);
    ((__nv_bfloat162*)h)[i * 2 + 1] = __halves2bfloat162(h2, h3);
    ((__nv_bfloat162*)l)[i * 2]     = __halves2bfloat162(
        __float2bfloat16(v.x - __bfloat162float(h0)),
        __float2bfloat16(v.y - __bfloat162float(h1)));
    ((__nv_bfloat162*)l)[i * 2 + 1] = __halves2bfloat162(
        __float2bfloat16(v.z - __bfloat162float(h2)),
        __float2bfloat16(v.w - __bfloat162float(h3)));
}

// W[d][e] fp32 -> Wt hi/lo [e][d] bf16 (768x768), 3 weights via blockIdx.z
__global__ void transW3(const float* __restrict__ W0, const float* __restrict__ W1,
                        const float* __restrict__ W2,
                        __nv_bfloat16* __restrict__ th, __nv_bfloat16* __restrict__ tl)
{
    __shared__ float t[32][33];
    const int tx = threadIdx.x, ty = threadIdx.y;      // block (32, 8)
    const int d0 = blockIdx.y * 32, e0 = blockIdx.x * 32;
    const float* W = (blockIdx.z == 0) ? W0 : (blockIdx.z == 1) ? W1 : W2;
    th += (size_t)blockIdx.z * DD * DD;
    tl += (size_t)blockIdx.z * DD * DD;
#pragma unroll
    for (int k = 0; k < 4; k++)
        t[ty + 8 * k][tx] = W[(size_t)(d0 + ty + 8 * k) * DD + e0 + tx];
    __syncthreads();
#pragma unroll
    for (int k = 0; k < 4; k++) {
        float v = t[tx][ty + 8 * k];
        __nv_bfloat16 h = __float2bfloat16(v);
        size_t o = (size_t)(e0 + ty + 8 * k) * DD + d0 + tx;
        th[o] = h;
        tl[o] = __float2bfloat16(v - __bfloat162float(h));
    }
}

// V hi/lo [b][l][d] -> Vt hi/lo [b][d][l]
__global__ void transV(const __nv_bfloat16* __restrict__ vh,
                       const __nv_bfloat16* __restrict__ vl,
                       __nv_bfloat16* __restrict__ oth,
                       __nv_bfloat16* __restrict__ otl)
{
    __shared__ __nv_bfloat16 th[32][33], tl[32][33];
    const int tx = threadIdx.x, ty = threadIdx.y;      // block (32, 8)
    const int d0 = blockIdx.x * 32, l0 = blockIdx.y * 32;
    const size_t zb = (size_t)blockIdx.z;
#pragma unroll
    for (int k = 0; k < 4; k++) {
        size_t o = (zb * LL + l0 + ty + 8 * k) * DD + d0 + tx;
        th[ty + 8 * k][tx] = vh[o];
        tl[ty + 8 * k][tx] = vl[o];
    }
    __syncthreads();
#pragma unroll
    for (int k = 0; k < 4; k++) {
        size_t o = (zb * DD + d0 + ty + 8 * k) * (size_t)LL + l0 + tx;
        oth[o] = th[tx][ty + 8 * k];
        otl[o] = tl[tx][ty + 8 * k];
    }
}

// ---------------- softmax: fp32 S row -> bf16 hi/lo P row -------------------
__global__ void __launch_bounds__(256)
softmax_split(const float* __restrict__ S,
              __nv_bfloat16* __restrict__ Ph, __nv_bfloat16* __restrict__ Pl)
{
    __shared__ float sh[LL];
    __shared__ float red[256];
    const float* p = S + (size_t)blockIdx.x * LL;
    const int tid = threadIdx.x;

    float m = -3.402823466e38f;
#pragma unroll
    for (int i = 0; i < LL / (256 * 4); i++) {
        int idx = (i * 256 + tid) * 4;
        float4 v = *(const float4*)(p + idx);
        *(float4*)&sh[idx] = v;
        m = fmaxf(m, fmaxf(fmaxf(v.x, v.y), fmaxf(v.z, v.w)));
    }
    red[tid] = m;
    __syncthreads();
#pragma unroll
    for (int s = 128; s > 0; s >>= 1) {
        if (tid < s) red[tid] = fmaxf(red[tid], red[tid + s]);
        __syncthreads();
    }
    m = red[0];
    __syncthreads();

    float sum = 0.0f;
#pragma unroll
    for (int i = 0; i < LL / (256 * 4); i++) {
        int idx = (i * 256 + tid) * 4;
        float4 v = *(float4*)&sh[idx];
        v.x = __expf(v.x - m); v.y = __expf(v.y - m);
        v.z = __expf(v.z - m); v.w = __expf(v.w - m);
        *(float4*)&sh[idx] = v;
        sum += v.x + v.y + v.z + v.w;
    }
    red[tid] = sum;
    __syncthreads();
#pragma unroll
    for (int s = 128; s > 0; s >>= 1) {
        if (tid < s) red[tid] += red[tid + s];
        __syncthreads();
    }
    const float inv = 1.0f / red[0];
    __syncthreads();

    __nv_bfloat162* ph = (__nv_bfloat162*)(Ph + (size_t)blockIdx.x * LL);
    __nv_bfloat162* pl = (__nv_bfloat162*)(Pl + (size_t)blockIdx.x * LL);
#pragma unroll
    for (int i = 0; i < LL / (256 * 4); i++) {
        int idx = (i * 256 + tid) * 4;
        float4 v = *(float4*)&sh[idx];
        v.x *= inv; v.y *= inv; v.z *= inv; v.w *= inv;
        __nv_bfloat16 h0 = __float2bfloat16(v.x), h1 = __float2bfloat16(v.y);
        __nv_bfloat16 h2 = __float2bfloat16(v.z), h3 = __float2bfloat16(v.w);
        ph[idx / 2]     = __halves2bfloat162(h0, h1);
        ph[idx / 2 + 1] = __halves2bfloat162(h2, h3);
        pl[idx / 2]     = __halves2bfloat162(
            __float2bfloat16(v.x - __bfloat162float(h0)),
            __float2bfloat16(v.y - __bfloat162float(h1)));
        pl[idx / 2 + 1] = __halves2bfloat162(
            __float2bfloat16(v.z - __bfloat162float(h2)),
            __float2bfloat16(v.w - __bfloat162float(h3)));
    }
}

// ---------------- orchestration ---------------------------------------------
extern "C" void kernel_launch(void* const* d_in, const int* in_sizes, int n_in,
                              void* d_out, int out_size)
{
    const float* X  = (const float*)d_in[0];
    const float* Wq = (const float*)d_in[1];
    const float* bq = (const float*)d_in[2];
    const float* Wk = (const float*)d_in[3];
    const float* bk = (const float*)d_in[4];
    const float* Wv = (const float*)d_in[5];
    const float* bv = (const float*)d_in[6];
    float* out = (float*)d_out;

    __nv_bfloat16 *Xh, *Xl, *Wth, *Wtl, *Qh, *Ql, *Kh, *Kl, *Vh, *Vl, *Vth, *Vtl, *Ph, *Pl;
    float* S;
    cudaGetSymbolAddress((void**)&Xh, g_Xh);   cudaGetSymbolAddress((void**)&Xl, g_Xl);
    cudaGetSymbolAddress((void**)&Wth, g_Wth); cudaGetSymbolAddress((void**)&Wtl, g_Wtl);
    cudaGetSymbolAddress((void**)&Qh, g_Qh);   cudaGetSymbolAddress((void**)&Ql, g_Ql);
    cudaGetSymbolAddress((void**)&Kh, g_Kh);   cudaGetSymbolAddress((void**)&Kl, g_Kl);
    cudaGetSymbolAddress((void**)&Vh, g_Vh);   cudaGetSymbolAddress((void**)&Vl, g_Vl);
    cudaGetSymbolAddress((void**)&Vth, g_Vth); cudaGetSymbolAddress((void**)&Vtl, g_Vtl);
    cudaGetSymbolAddress((void**)&Ph, g_Ph);   cudaGetSymbolAddress((void**)&Pl, g_Pl);
    cudaGetSymbolAddress((void**)&S, g_S);

    cudaFuncSetAttribute(gemm_mma<0>, cudaFuncAttributeMaxDynamicSharedMemorySize, SMEM_BYTES);
    cudaFuncSetAttribute(gemm_mma<2>, cudaFuncAttributeMaxDynamicSharedMemorySize, SMEM_BYTES);

    EpiPtrs3 none{};

    // 1) split X into bf16 hi/lo
    {
        int n4 = ML * DD / 4;
        convert_split<<<(n4 + 255) / 256, 256>>>(X, Xh, Xl, n4);
    }
    // 2) transpose+split weights (one launch, z = q/k/v)
    {
        dim3 g(DD / 32, DD / 32, 3), b(32, 8);
        transW3<<<g, b>>>(Wq, Wk, Wv, Wth, Wtl);
    }
    // 3) projections, one launch (z selects weight/bias/output)
    {
        EpiPtrs3 ep;
        ep.p[0] = {bq, Qh, Ql};
        ep.p[1] = {bk, Kh, Kl};
        ep.p[2] = {bv, Vh, Vl};
        dim3 g(DD / 128, ML / 256, 3);
        gemm_mma<0><<<g, 256, SMEM_BYTES>>>(Xh, Xl, Wth, Wtl, ep, nullptr,
            DD, DD, 0, (long long)DD * DD, 0);
    }
    // 4) transpose V hi/lo per batch -> [b][d][l]
    {
        dim3 g(DD / 32, LL / 32, BB), b(32, 8);
        transV<<<g, b>>>(Vh, Vl, Vth, Vtl);
    }
    // 5) logits: S[b] = Q[b] @ K[b]^T (fp32 out)
    {
        dim3 g(LL / 128, LL / 256, BB);
        gemm_mma<2><<<g, 256, SMEM_BYTES>>>(Qh, Ql, Kh, Kl, none, S,
            DD, LL, (long long)LL * DD, (long long)LL * DD, (long long)LL * LL);
    }
    // 6) softmax rows -> bf16 hi/lo P
    softmax_split<<<ML, 256>>>(S, Ph, Pl);
    // 7) output: O[b] = P[b] @ Vt[b]^T (fp32 out)
    {
        dim3 g(DD / 128, LL / 256, BB);
        gemm_mma<2><<<g, 256, SMEM_BYTES>>>(Ph, Pl, Vth, Vtl, none, out,
            LL, DD, (long long)LL * LL, (long long)DD * LL, (long long)LL * DD);
    }
}

// round 6
// speedup vs baseline: 4.6534x; 1.3208x over previous
#include <cuda_runtime.h>
#include <cuda_fp16.h>
#include <cstdint>

#define BB 4
#define LL 4096
#define DD 768
#define ML (BB*LL)

// ---------------- scratch (__device__ globals; allocation-free contract) ----
__device__ __half g_Xh[(size_t)ML * DD], g_Xl[(size_t)ML * DD];
__device__ __half g_Wth[3][(size_t)DD * DD], g_Wtl[3][(size_t)DD * DD];
__device__ __half g_Qh[(size_t)ML * DD], g_Ql[(size_t)ML * DD];
__device__ __half g_Kh[(size_t)ML * DD], g_Kl[(size_t)ML * DD];
__device__ __half g_Vh[(size_t)ML * DD], g_Vl[(size_t)ML * DD];
__device__ __half g_Vth[(size_t)ML * DD];
__device__ float  g_S [(size_t)BB * LL * LL];
__device__ __half g_P [(size_t)BB * LL * LL];

// ---------------- helpers (base-family ISA only) -----------------------------
__device__ __forceinline__ uint32_t s2u(const void* p) {
    uint32_t a;
    asm("{ .reg .u64 t; cvta.to.shared.u64 t, %1; cvt.u32.u64 %0, t; }"
        : "=r"(a) : "l"(p));
    return a;
}
__device__ __forceinline__ uint32_t sw128(uint32_t off) {
    return off ^ ((off >> 3) & 0x70);
}
__device__ __forceinline__ void cp16(uint32_t saddr, const void* g) {
    asm volatile("cp.async.cg.shared.global [%0], [%1], 16;" :: "r"(saddr), "l"(g));
}
__device__ __forceinline__ void cp_commit() {
    asm volatile("cp.async.commit_group;");
}
template <int N>
__device__ __forceinline__ void cp_wait() {
    asm volatile("cp.async.wait_group %0;" :: "n"(N));
}
__device__ __forceinline__ void ldm_x4(uint32_t* r, uint32_t addr) {
    asm volatile("ldmatrix.sync.aligned.m8n8.x4.shared.b16 {%0,%1,%2,%3}, [%4];"
                 : "=r"(r[0]), "=r"(r[1]), "=r"(r[2]), "=r"(r[3]) : "r"(addr));
}
__device__ __forceinline__ void mma_f16(float* c, const uint32_t* a, const uint32_t* b) {
    asm volatile(
        "mma.sync.aligned.m16n8k16.row.col.f32.f16.f16.f32 "
        "{%0,%1,%2,%3}, {%4,%5,%6,%7}, {%8,%9}, {%0,%1,%2,%3};"
        : "+f"(c[0]), "+f"(c[1]), "+f"(c[2]), "+f"(c[3])
        : "r"(a[0]), "r"(a[1]), "r"(a[2]), "r"(a[3]), "r"(b[0]), "r"(b[1]));
}

// ---------------- fp16 HMMA GEMM --------------------------------------------
// C[M,N] = sum_k A[m,k]*B[n,k]; A,B K-major fp16 (hi/lo if TERMS==3).
// 256x128 CTA tile (8 warps, 64x64 per warp), 64-k chunks, 2-stage pipeline.
// TERMS==3: Ah*Bh + Ah*Bl + Al*Bh (split-fp32 numerics).
// TERMS==1: Ah*Bh only.
// EPI=0: +bias (per-z ptrs), fp16 hi/lo out. EPI=2: fp32 out (+z*strC).
struct EpiPtrs { const float* bias; __half* ch; __half* cl; };
struct EpiPtrs3 { EpiPtrs p[3]; };

template <int ROWS>
__device__ __forceinline__ void load_tile(const __half* __restrict__ g,
                                          long long ld, uint32_t sdst, int tid) {
#pragma unroll
    for (int it = 0; it < ROWS * 8 / 256; it++) {
        int u = it * 256 + tid;            // ROWS rows x 8 16B-segments
        int row = u >> 3, seg = u & 7;
        cp16(sdst + sw128(row * 128 + seg * 16), g + (long long)row * ld + seg * 8);
    }
}

template <int EPI, int TERMS>
__global__ void __launch_bounds__(256, 1)
gemm_mma(const __half* __restrict__ Ah, const __half* __restrict__ Al,
         const __half* __restrict__ Bh, const __half* __restrict__ Bl,
         EpiPtrs3 EP, void* __restrict__ C0,
         int K, int ldC,
         long long strA, long long strB, long long strC)
{
    constexpr int A_BYTES = 256 * 128;
    constexpr int B_BYTES = 128 * 128;
    constexpr int OFF_AH = 0;
    constexpr int OFF_AL = A_BYTES;
    constexpr int OFF_BH = (TERMS == 3) ? 2 * A_BYTES : A_BYTES;
    constexpr int OFF_BL = 2 * A_BYTES + B_BYTES;
    constexpr int STAGE  = (TERMS == 3) ? (2 * A_BYTES + 2 * B_BYTES)
                                        : (A_BYTES + B_BYTES);

    extern __shared__ char smem[];
    const uint32_t sbase = s2u(smem);
    const int tid  = threadIdx.x;
    const int lane = tid & 31;
    const int warp = tid >> 5;
    const int wm = warp >> 1;   // 0..3  (64-row slice)
    const int wn = warp & 1;    // 0..1  (64-col slice)
    const int m0 = blockIdx.y * 256, n0 = blockIdx.x * 128;
    const long long z = blockIdx.z;

    const __half* aH = Ah + z * strA + (long long)m0 * K;
    const __half* aL = (TERMS == 3) ? Al + z * strA + (long long)m0 * K : nullptr;
    const __half* bH = Bh + z * strB + (long long)n0 * K;
    const __half* bL = (TERMS == 3) ? Bl + z * strB + (long long)n0 * K : nullptr;

    float acc[4][8][4];
#pragma unroll
    for (int mt = 0; mt < 4; mt++)
#pragma unroll
        for (int nt = 0; nt < 8; nt++)
#pragma unroll
            for (int i = 0; i < 4; i++) acc[mt][nt][i] = 0.0f;

    const int nch = K >> 6;

    // prologue: chunk 0
    {
        load_tile<256>(aH, K, sbase + OFF_AH, tid);
        if (TERMS == 3) load_tile<256>(aL, K, sbase + OFF_AL, tid);
        load_tile<128>(bH, K, sbase + OFF_BH, tid);
        if (TERMS == 3) load_tile<128>(bL, K, sbase + OFF_BL, tid);
        cp_commit();
    }

    for (int c = 0; c < nch; c++) {
        cp_wait<0>();          // chunk c resident
        __syncthreads();       // everyone done with chunk c-1 -> other stage free

        if (c + 1 < nch) {
            uint32_t sb = sbase + ((c + 1) & 1) * STAGE;
            load_tile<256>(aH + (c + 1) * 64, K, sb + OFF_AH, tid);
            if (TERMS == 3) load_tile<256>(aL + (c + 1) * 64, K, sb + OFF_AL, tid);
            load_tile<128>(bH + (c + 1) * 64, K, sb + OFF_BH, tid);
            if (TERMS == 3) load_tile<128>(bL + (c + 1) * 64, K, sb + OFF_BL, tid);
            cp_commit();
        }

        const uint32_t sb  = sbase + (c & 1) * STAGE;
        const uint32_t sAh = sb + OFF_AH, sAl = sb + OFF_AL;
        const uint32_t sBh = sb + OFF_BH, sBl = sb + OFF_BL;

#pragma unroll
        for (int ks = 0; ks < 4; ks++) {
            uint32_t ah[4][4], al[4][4];
#pragma unroll
            for (int mt = 0; mt < 4; mt++) {
                uint32_t off = sw128((uint32_t)((wm * 64 + mt * 16 + (lane & 15)) * 128
                                                + (ks * 2 + (lane >> 4)) * 16));
                ldm_x4(ah[mt], sAh + off);
                if (TERMS == 3) ldm_x4(al[mt], sAl + off);
            }
            const int g = lane >> 3;
#pragma unroll
            for (int np = 0; np < 4; np++) {
                uint32_t boff = sw128((uint32_t)(
                    (wn * 64 + np * 16 + ((g >> 1) << 3) + (lane & 7)) * 128
                    + ks * 32 + (g & 1) * 16));
                uint32_t bh[4], bl[4];
                ldm_x4(bh, sBh + boff);
                if (TERMS == 3) ldm_x4(bl, sBl + boff);
#pragma unroll
                for (int mt = 0; mt < 4; mt++) {
                    mma_f16(acc[mt][np * 2 + 0], ah[mt], bh + 0);
                    mma_f16(acc[mt][np * 2 + 1], ah[mt], bh + 2);
                    if (TERMS == 3) {
                        mma_f16(acc[mt][np * 2 + 0], ah[mt], bl + 0);
                        mma_f16(acc[mt][np * 2 + 1], ah[mt], bl + 2);
                        mma_f16(acc[mt][np * 2 + 0], al[mt], bh + 0);
                        mma_f16(acc[mt][np * 2 + 1], al[mt], bh + 2);
                    }
                }
            }
        }
    }

    // ----- epilogue -----
    const int rbase = m0 + wm * 64 + (lane >> 2);
    const int cbase = n0 + wn * 64 + 2 * (lane & 3);
    if (EPI == 0) {
        const EpiPtrs e = EP.p[z];
#pragma unroll
        for (int mt = 0; mt < 4; mt++)
#pragma unroll
            for (int nt = 0; nt < 8; nt++) {
                int col = cbase + nt * 8;
                float b0 = e.bias[col], b1 = e.bias[col + 1];
#pragma unroll
                for (int half_ = 0; half_ < 2; half_++) {
                    int r = rbase + mt * 16 + half_ * 8;
                    float v0 = acc[mt][nt][half_ * 2 + 0] + b0;
                    float v1 = acc[mt][nt][half_ * 2 + 1] + b1;
                    __half h0 = __float2half(v0);
                    __half h1 = __float2half(v1);
                    __half l0 = __float2half(v0 - __half2float(h0));
                    __half l1 = __float2half(v1 - __half2float(h1));
                    *(__half2*)(e.ch + (size_t)r * ldC + col) = __halves2half2(h0, h1);
                    *(__half2*)(e.cl + (size_t)r * ldC + col) = __halves2half2(l0, l1);
                }
            }
    } else {
        float* Cf = (float*)C0 + z * strC;
#pragma unroll
        for (int mt = 0; mt < 4; mt++)
#pragma unroll
            for (int nt = 0; nt < 8; nt++) {
                int col = cbase + nt * 8;
#pragma unroll
                for (int half_ = 0; half_ < 2; half_++) {
                    int r = rbase + mt * 16 + half_ * 8;
                    float2 v;
                    v.x = acc[mt][nt][half_ * 2 + 0];
                    v.y = acc[mt][nt][half_ * 2 + 1];
                    *(float2*)(Cf + (size_t)r * ldC + col) = v;
                }
            }
    }
}

static constexpr int SMEM3 = 2 * (2 * 256 * 128 + 2 * 128 * 128);  // 192 KB
static constexpr int SMEM1 = 2 * (256 * 128 + 128 * 128);          // 96 KB

// ---------------- prep kernels ----------------------------------------------
__global__ void convert_split(const float* __restrict__ x,
                              __half* __restrict__ h,
                              __half* __restrict__ l, int n4)
{
    int i = blockIdx.x * blockDim.x + threadIdx.x;
    if (i >= n4) return;
    float4 v = ((const float4*)x)[i];
    __half h0 = __float2half(v.x), h1 = __float2half(v.y);
    __half h2 = __float2half(v.z), h3 = __float2half(v.w);
    ((__half2*)h)[i * 2]     = __halves2half2(h0, h1);
    ((__half2*)h)[i * 2 + 1] = __halves2half2(h2, h3);
    ((__half2*)l)[i * 2]     = __halves2half2(
        __float2half(v.x - __half2float(h0)),
        __float2half(v.y - __half2float(h1)));
    ((__half2*)l)[i * 2 + 1] = __halves2half2(
        __float2half(v.z - __half2float(h2)),
        __float2half(v.w - __half2float(h3)));
}

// W[d][e] fp32 -> Wt hi/lo [e][d] fp16 (768x768), 3 weights via blockIdx.z
__global__ void transW3(const float* __restrict__ W0, const float* __restrict__ W1,
                        const float* __restrict__ W2,
                        __half* __restrict__ th, __half* __restrict__ tl)
{
    __shared__ float t[32][33];
    const int tx = threadIdx.x, ty = threadIdx.y;      // block (32, 8)
    const int d0 = blockIdx.y * 32, e0 = blockIdx.x * 32;
    const float* W = (blockIdx.z == 0) ? W0 : (blockIdx.z == 1) ? W1 : W2;
    th += (size_t)blockIdx.z * DD * DD;
    tl += (size_t)blockIdx.z * DD * DD;
#pragma unroll
    for (int k = 0; k < 4; k++)
        t[ty + 8 * k][tx] = W[(size_t)(d0 + ty + 8 * k) * DD + e0 + tx];
    __syncthreads();
#pragma unroll
    for (int k = 0; k < 4; k++) {
        float v = t[tx][ty + 8 * k];
        __half h = __float2half(v);
        size_t o = (size_t)(e0 + ty + 8 * k) * DD + d0 + tx;
        th[o] = h;
        tl[o] = __float2half(v - __half2float(h));
    }
}

// V hi [b][l][d] -> Vt [b][d][l] (single fp16)
__global__ void transVh(const __half* __restrict__ vh, __half* __restrict__ ot)
{
    __shared__ __half t[32][33];
    const int tx = threadIdx.x, ty = threadIdx.y;      // block (32, 8)
    const int d0 = blockIdx.x * 32, l0 = blockIdx.y * 32;
    const size_t zb = (size_t)blockIdx.z;
#pragma unroll
    for (int k = 0; k < 4; k++)
        t[ty + 8 * k][tx] = vh[(zb * LL + l0 + ty + 8 * k) * DD + d0 + tx];
    __syncthreads();
#pragma unroll
    for (int k = 0; k < 4; k++)
        ot[(zb * DD + d0 + ty + 8 * k) * (size_t)LL + l0 + tx] = t[tx][ty + 8 * k];
}

// ---------------- softmax: fp32 S row -> single fp16 P row ------------------
__global__ void __launch_bounds__(256)
softmax_h(const float* __restrict__ S, __half* __restrict__ P)
{
    __shared__ float sh[LL];
    __shared__ float red[256];
    const float* p = S + (size_t)blockIdx.x * LL;
    const int tid = threadIdx.x;

    float m = -3.402823466e38f;
#pragma unroll
    for (int i = 0; i < LL / (256 * 4); i++) {
        int idx = (i * 256 + tid) * 4;
        float4 v = *(const float4*)(p + idx);
        *(float4*)&sh[idx] = v;
        m = fmaxf(m, fmaxf(fmaxf(v.x, v.y), fmaxf(v.z, v.w)));
    }
    red[tid] = m;
    __syncthreads();
#pragma unroll
    for (int s = 128; s > 0; s >>= 1) {
        if (tid < s) red[tid] = fmaxf(red[tid], red[tid + s]);
        __syncthreads();
    }
    m = red[0];
    __syncthreads();

    float sum = 0.0f;
#pragma unroll
    for (int i = 0; i < LL / (256 * 4); i++) {
        int idx = (i * 256 + tid) * 4;
        float4 v = *(float4*)&sh[idx];
        v.x = __expf(v.x - m); v.y = __expf(v.y - m);
        v.z = __expf(v.z - m); v.w = __expf(v.w - m);
        *(float4*)&sh[idx] = v;
        sum += v.x + v.y + v.z + v.w;
    }
    red[tid] = sum;
    __syncthreads();
#pragma unroll
    for (int s = 128; s > 0; s >>= 1) {
        if (tid < s) red[tid] += red[tid + s];
        __syncthreads();
    }
    const float inv = 1.0f / red[0];
    __syncthreads();

    __half2* ph = (__half2*)(P + (size_t)blockIdx.x * LL);
#pragma unroll
    for (int i = 0; i < LL / (256 * 4); i++) {
        int idx = (i * 256 + tid) * 4;
        float4 v = *(float4*)&sh[idx];
        ph[idx / 2]     = __floats2half2_rn(v.x * inv, v.y * inv);
        ph[idx / 2 + 1] = __floats2half2_rn(v.z * inv, v.w * inv);
    }
}

// ---------------- orchestration ---------------------------------------------
extern "C" void kernel_launch(void* const* d_in, const int* in_sizes, int n_in,
                              void* d_out, int out_size)
{
    const float* X  = (const float*)d_in[0];
    const float* Wq = (const float*)d_in[1];
    const float* bq = (const float*)d_in[2];
    const float* Wk = (const float*)d_in[3];
    const float* bk = (const float*)d_in[4];
    const float* Wv = (const float*)d_in[5];
    const float* bv = (const float*)d_in[6];
    float* out = (float*)d_out;

    __half *Xh, *Xl, *Wth, *Wtl, *Qh, *Ql, *Kh, *Kl, *Vh, *Vl, *Vth, *P;
    float* S;
    cudaGetSymbolAddress((void**)&Xh, g_Xh);   cudaGetSymbolAddress((void**)&Xl, g_Xl);
    cudaGetSymbolAddress((void**)&Wth, g_Wth); cudaGetSymbolAddress((void**)&Wtl, g_Wtl);
    cudaGetSymbolAddress((void**)&Qh, g_Qh);   cudaGetSymbolAddress((void**)&Ql, g_Ql);
    cudaGetSymbolAddress((void**)&Kh, g_Kh);   cudaGetSymbolAddress((void**)&Kl, g_Kl);
    cudaGetSymbolAddress((void**)&Vh, g_Vh);   cudaGetSymbolAddress((void**)&Vl, g_Vl);
    cudaGetSymbolAddress((void**)&Vth, g_Vth);
    cudaGetSymbolAddress((void**)&P, g_P);
    cudaGetSymbolAddress((void**)&S, g_S);

    cudaFuncSetAttribute(gemm_mma<0, 3>, cudaFuncAttributeMaxDynamicSharedMemorySize, SMEM3);
    cudaFuncSetAttribute(gemm_mma<2, 3>, cudaFuncAttributeMaxDynamicSharedMemorySize, SMEM3);
    cudaFuncSetAttribute(gemm_mma<2, 1>, cudaFuncAttributeMaxDynamicSharedMemorySize, SMEM1);

    EpiPtrs3 none{};

    // 1) split X into fp16 hi/lo
    {
        int n4 = ML * DD / 4;
        convert_split<<<(n4 + 255) / 256, 256>>>(X, Xh, Xl, n4);
    }
    // 2) transpose+split weights (one launch, z = q/k/v)
    {
        dim3 g(DD / 32, DD / 32, 3), b(32, 8);
        transW3<<<g, b>>>(Wq, Wk, Wv, Wth, Wtl);
    }
    // 3) projections, one launch (z selects weight/bias/output), fp16 3-term
    {
        EpiPtrs3 ep;
        ep.p[0] = {bq, Qh, Ql};
        ep.p[1] = {bk, Kh, Kl};
        ep.p[2] = {bv, Vh, Vl};
        dim3 g(DD / 128, ML / 256, 3);
        gemm_mma<0, 3><<<g, 256, SMEM3>>>(Xh, Xl, Wth, Wtl, ep, nullptr,
            DD, DD, 0, (long long)DD * DD, 0);
    }
    // 4) transpose V (hi only) per batch -> [b][d][l]
    {
        dim3 g(DD / 32, LL / 32, BB), b(32, 8);
        transVh<<<g, b>>>(Vh, Vth);
    }
    // 5) logits: S[b] = Q[b] @ K[b]^T (fp16 3-term, fp32 out)
    {
        dim3 g(LL / 128, LL / 256, BB);
        gemm_mma<2, 3><<<g, 256, SMEM3>>>(Qh, Ql, Kh, Kl, none, S,
            DD, LL, (long long)LL * DD, (long long)LL * DD, (long long)LL * LL);
    }
    // 6) softmax rows -> single fp16 P
    softmax_h<<<ML, 256>>>(S, P);
    // 7) output: O[b] = P[b] @ Vt[b]^T (fp16 1-term, fp32 out)
    {
        dim3 g(DD / 128, LL / 256, BB);
        gemm_mma<2, 1><<<g, 256, SMEM1>>>(P, nullptr, Vth, nullptr, none, out,
            LL, DD, (long long)LL * LL, (long long)DD * LL, (long long)LL * DD);
    }
}

// round 7
// speedup vs baseline: 4.7942x; 1.0303x over previous
#include <cuda_runtime.h>
#include <cuda_fp16.h>
#include <cstdint>

#define BB 4
#define LL 4096
#define DD 768
#define ML (BB*LL)

// ---------------- scratch (__device__ globals; allocation-free contract) ----
__device__ __half g_Xh[(size_t)ML * DD], g_Xl[(size_t)ML * DD];
__device__ __half g_Wth[3][(size_t)DD * DD], g_Wtl[3][(size_t)DD * DD];
__device__ __half g_Qh[(size_t)ML * DD], g_Ql[(size_t)ML * DD];
__device__ __half g_Kh[(size_t)ML * DD], g_Kl[(size_t)ML * DD];
__device__ __half g_Vt[(size_t)ML * DD];              // [b][d][l] fp16
__device__ float  g_S [(size_t)BB * LL * LL];
__device__ __half g_P [(size_t)BB * LL * LL];

// ---------------- helpers (base-family ISA only) -----------------------------
__device__ __forceinline__ uint32_t s2u(const void* p) {
    uint32_t a;
    asm("{ .reg .u64 t; cvta.to.shared.u64 t, %1; cvt.u32.u64 %0, t; }"
        : "=r"(a) : "l"(p));
    return a;
}
__device__ __forceinline__ uint32_t sw128(uint32_t off) {
    return off ^ ((off >> 3) & 0x70);
}
__device__ __forceinline__ void cp16(uint32_t saddr, const void* g) {
    asm volatile("cp.async.cg.shared.global [%0], [%1], 16;" :: "r"(saddr), "l"(g));
}
__device__ __forceinline__ void cp_commit() {
    asm volatile("cp.async.commit_group;");
}
template <int N>
__device__ __forceinline__ void cp_wait() {
    asm volatile("cp.async.wait_group %0;" :: "n"(N));
}
__device__ __forceinline__ void ldm_x4(uint32_t* r, uint32_t addr) {
    asm volatile("ldmatrix.sync.aligned.m8n8.x4.shared.b16 {%0,%1,%2,%3}, [%4];"
                 : "=r"(r[0]), "=r"(r[1]), "=r"(r[2]), "=r"(r[3]) : "r"(addr));
}
__device__ __forceinline__ void mma_f16(float* c, const uint32_t* a, const uint32_t* b) {
    asm volatile(
        "mma.sync.aligned.m16n8k16.row.col.f32.f16.f16.f32 "
        "{%0,%1,%2,%3}, {%4,%5,%6,%7}, {%8,%9}, {%0,%1,%2,%3};"
        : "+f"(c[0]), "+f"(c[1]), "+f"(c[2]), "+f"(c[3])
        : "r"(a[0]), "r"(a[1]), "r"(a[2]), "r"(a[3]), "r"(b[0]), "r"(b[1]));
}

// ---------------- fp16 HMMA GEMM --------------------------------------------
// C[M,N] = sum_k A[m,k]*B[n,k]; A,B K-major fp16 (hi/lo if TERMS==3).
// 256x128 CTA tile (8 warps, 64x64 per warp), 64-k chunks, 2-stage pipeline.
// EPI=0: +bias; z<2 -> fp16 hi/lo out; z==2 -> transpose-staged single fp16
//        out to Vt[b][d][l]. EPI=2: fp32 out (+z*strC).
struct EpiPtrs { const float* bias; __half* ch; __half* cl; };
struct EpiPtrs3 { EpiPtrs p[3]; };

// transpose staging: 128 cols x 256 rows fp16, row stride 264 halfs (16B-ok)
static constexpr int TPAD = 264;

template <int ROWS>
__device__ __forceinline__ void load_tile(const __half* __restrict__ g,
                                          long long ld, uint32_t sdst, int tid) {
#pragma unroll
    for (int it = 0; it < ROWS * 8 / 256; it++) {
        int u = it * 256 + tid;            // ROWS rows x 8 16B-segments
        int row = u >> 3, seg = u & 7;
        cp16(sdst + sw128(row * 128 + seg * 16), g + (long long)row * ld + seg * 8);
    }
}

template <int EPI, int TERMS>
__global__ void __launch_bounds__(256, 1)
gemm_mma(const __half* __restrict__ Ah, const __half* __restrict__ Al,
         const __half* __restrict__ Bh, const __half* __restrict__ Bl,
         EpiPtrs3 EP, void* __restrict__ C0,
         int K, int ldC,
         long long strA, long long strB, long long strC)
{
    constexpr int A_BYTES = 256 * 128;
    constexpr int B_BYTES = 128 * 128;
    constexpr int OFF_AH = 0;
    constexpr int OFF_AL = A_BYTES;
    constexpr int OFF_BH = (TERMS == 3) ? 2 * A_BYTES : A_BYTES;
    constexpr int OFF_BL = 2 * A_BYTES + B_BYTES;
    constexpr int STAGE  = (TERMS == 3) ? (2 * A_BYTES + 2 * B_BYTES)
                                        : (A_BYTES + B_BYTES);

    extern __shared__ char smem[];
    const uint32_t sbase = s2u(smem);
    const int tid  = threadIdx.x;
    const int lane = tid & 31;
    const int warp = tid >> 5;
    const int wm = warp >> 1;   // 0..3  (64-row slice)
    const int wn = warp & 1;    // 0..1  (64-col slice)
    const int m0 = blockIdx.y * 256, n0 = blockIdx.x * 128;
    const long long z = blockIdx.z;

    const __half* aH = Ah + z * strA + (long long)m0 * K;
    const __half* aL = (TERMS == 3) ? Al + z * strA + (long long)m0 * K : nullptr;
    const __half* bH = Bh + z * strB + (long long)n0 * K;
    const __half* bL = (TERMS == 3) ? Bl + z * strB + (long long)n0 * K : nullptr;

    float acc[4][8][4];
#pragma unroll
    for (int mt = 0; mt < 4; mt++)
#pragma unroll
        for (int nt = 0; nt < 8; nt++)
#pragma unroll
            for (int i = 0; i < 4; i++) acc[mt][nt][i] = 0.0f;

    const int nch = K >> 6;

    // prologue: chunk 0
    {
        load_tile<256>(aH, K, sbase + OFF_AH, tid);
        if (TERMS == 3) load_tile<256>(aL, K, sbase + OFF_AL, tid);
        load_tile<128>(bH, K, sbase + OFF_BH, tid);
        if (TERMS == 3) load_tile<128>(bL, K, sbase + OFF_BL, tid);
        cp_commit();
    }

    for (int c = 0; c < nch; c++) {
        cp_wait<0>();          // chunk c resident
        __syncthreads();       // everyone done with chunk c-1 -> other stage free

        if (c + 1 < nch) {
            uint32_t sb = sbase + ((c + 1) & 1) * STAGE;
            load_tile<256>(aH + (c + 1) * 64, K, sb + OFF_AH, tid);
            if (TERMS == 3) load_tile<256>(aL + (c + 1) * 64, K, sb + OFF_AL, tid);
            load_tile<128>(bH + (c + 1) * 64, K, sb + OFF_BH, tid);
            if (TERMS == 3) load_tile<128>(bL + (c + 1) * 64, K, sb + OFF_BL, tid);
            cp_commit();
        }

        const uint32_t sb  = sbase + (c & 1) * STAGE;
        const uint32_t sAh = sb + OFF_AH, sAl = sb + OFF_AL;
        const uint32_t sBh = sb + OFF_BH, sBl = sb + OFF_BL;

#pragma unroll
        for (int ks = 0; ks < 4; ks++) {
            uint32_t ah[4][4], al[4][4];
#pragma unroll
            for (int mt = 0; mt < 4; mt++) {
                uint32_t off = sw128((uint32_t)((wm * 64 + mt * 16 + (lane & 15)) * 128
                                                + (ks * 2 + (lane >> 4)) * 16));
                ldm_x4(ah[mt], sAh + off);
                if (TERMS == 3) ldm_x4(al[mt], sAl + off);
            }
            const int g = lane >> 3;
#pragma unroll
            for (int np = 0; np < 4; np++) {
                uint32_t boff = sw128((uint32_t)(
                    (wn * 64 + np * 16 + ((g >> 1) << 3) + (lane & 7)) * 128
                    + ks * 32 + (g & 1) * 16));
                uint32_t bh[4], bl[4];
                ldm_x4(bh, sBh + boff);
                if (TERMS == 3) ldm_x4(bl, sBl + boff);
#pragma unroll
                for (int mt = 0; mt < 4; mt++) {
                    mma_f16(acc[mt][np * 2 + 0], ah[mt], bh + 0);
                    mma_f16(acc[mt][np * 2 + 1], ah[mt], bh + 2);
                    if (TERMS == 3) {
                        mma_f16(acc[mt][np * 2 + 0], ah[mt], bl + 0);
                        mma_f16(acc[mt][np * 2 + 1], ah[mt], bl + 2);
                        mma_f16(acc[mt][np * 2 + 0], al[mt], bh + 0);
                        mma_f16(acc[mt][np * 2 + 1], al[mt], bh + 2);
                    }
                }
            }
        }
    }

    // ----- epilogue -----
    const int rloc = wm * 64 + (lane >> 2);          // 0..255 within tile
    const int cloc = wn * 64 + 2 * (lane & 3);       // 0..127 within tile
    if (EPI == 0) {
        const EpiPtrs e = EP.p[z];
        if (z == 2) {
            // V: stage fp16 transposed in SMEM, write Vt[b][d][l] coalesced
            __half* ts = (__half*)smem;
            __syncthreads();   // mainloop SMEM reuse
#pragma unroll
            for (int mt = 0; mt < 4; mt++)
#pragma unroll
                for (int nt = 0; nt < 8; nt++) {
                    int col = cloc + nt * 8;
                    float b0 = e.bias[n0 + col], b1 = e.bias[n0 + col + 1];
#pragma unroll
                    for (int half_ = 0; half_ < 2; half_++) {
                        int r = rloc + mt * 16 + half_ * 8;
                        ts[(size_t)col * TPAD + r] =
                            __float2half(acc[mt][nt][half_ * 2 + 0] + b0);
                        ts[(size_t)(col + 1) * TPAD + r] =
                            __float2half(acc[mt][nt][half_ * 2 + 1] + b1);
                    }
                }
            __syncthreads();
            const int batch = m0 >> 12;              // 4096 rows per batch
            const int l0 = m0 & 4095;
            __half* vt = e.ch + ((size_t)batch * DD) * LL;
#pragma unroll
            for (int it = 0; it < 16; it++) {
                int u = it * 256 + tid;              // 128 rows x 32 uint4
                int d = u >> 5, seg = u & 31;
                uint4 v = *(const uint4*)(ts + (size_t)d * TPAD + seg * 8);
                *(uint4*)(vt + (size_t)(n0 + d) * LL + l0 + seg * 8) = v;
            }
        } else {
#pragma unroll
            for (int mt = 0; mt < 4; mt++)
#pragma unroll
                for (int nt = 0; nt < 8; nt++) {
                    int col = n0 + cloc + nt * 8;
                    float b0 = e.bias[col], b1 = e.bias[col + 1];
#pragma unroll
                    for (int half_ = 0; half_ < 2; half_++) {
                        int r = m0 + rloc + mt * 16 + half_ * 8;
                        float v0 = acc[mt][nt][half_ * 2 + 0] + b0;
                        float v1 = acc[mt][nt][half_ * 2 + 1] + b1;
                        __half h0 = __float2half(v0);
                        __half h1 = __float2half(v1);
                        __half l0 = __float2half(v0 - __half2float(h0));
                        __half l1 = __float2half(v1 - __half2float(h1));
                        *(__half2*)(e.ch + (size_t)r * ldC + col) = __halves2half2(h0, h1);
                        *(__half2*)(e.cl + (size_t)r * ldC + col) = __halves2half2(l0, l1);
                    }
                }
        }
    } else {
        float* Cf = (float*)C0 + z * strC;
#pragma unroll
        for (int mt = 0; mt < 4; mt++)
#pragma unroll
            for (int nt = 0; nt < 8; nt++) {
                int col = n0 + cloc + nt * 8;
#pragma unroll
                for (int half_ = 0; half_ < 2; half_++) {
                    int r = m0 + rloc + mt * 16 + half_ * 8;
                    float2 v;
                    v.x = acc[mt][nt][half_ * 2 + 0];
                    v.y = acc[mt][nt][half_ * 2 + 1];
                    *(float2*)(Cf + (size_t)r * ldC + col) = v;
                }
            }
    }
}

static constexpr int SMEM3 = 2 * (2 * 256 * 128 + 2 * 128 * 128);  // 192 KB
static constexpr int SMEM1 = 2 * (256 * 128 + 128 * 128);          // 96 KB

// ---------------- prep kernels ----------------------------------------------
__global__ void convert_split(const float* __restrict__ x,
                              __half* __restrict__ h,
                              __half* __restrict__ l, int n4)
{
    int i = blockIdx.x * blockDim.x + threadIdx.x;
    if (i >= n4) return;
    float4 v = ((const float4*)x)[i];
    __half h0 = __float2half(v.x), h1 = __float2half(v.y);
    __half h2 = __float2half(v.z), h3 = __float2half(v.w);
    ((__half2*)h)[i * 2]     = __halves2half2(h0, h1);
    ((__half2*)h)[i * 2 + 1] = __halves2half2(h2, h3);
    ((__half2*)l)[i * 2]     = __halves2half2(
        __float2half(v.x - __half2float(h0)),
        __float2half(v.y - __half2float(h1)));
    ((__half2*)l)[i * 2 + 1] = __halves2half2(
        __float2half(v.z - __half2float(h2)),
        __float2half(v.w - __half2float(h3)));
}

// W[d][e] fp32 -> Wt hi/lo [e][d] fp16 (768x768), 3 weights via blockIdx.z
__global__ void transW3(const float* __restrict__ W0, const float* __restrict__ W1,
                        const float* __restrict__ W2,
                        __half* __restrict__ th, __half* __restrict__ tl)
{
    __shared__ float t[32][33];
    const int tx = threadIdx.x, ty = threadIdx.y;      // block (32, 8)
    const int d0 = blockIdx.y * 32, e0 = blockIdx.x * 32;
    const float* W = (blockIdx.z == 0) ? W0 : (blockIdx.z == 1) ? W1 : W2;
    th += (size_t)blockIdx.z * DD * DD;
    tl += (size_t)blockIdx.z * DD * DD;
#pragma unroll
    for (int k = 0; k < 4; k++)
        t[ty + 8 * k][tx] = W[(size_t)(d0 + ty + 8 * k) * DD + e0 + tx];
    __syncthreads();
#pragma unroll
    for (int k = 0; k < 4; k++) {
        float v = t[tx][ty + 8 * k];
        __half h = __float2half(v);
        size_t o = (size_t)(e0 + ty + 8 * k) * DD + d0 + tx;
        th[o] = h;
        tl[o] = __float2half(v - __half2float(h));
    }
}

// ---------------- softmax: register-resident, fp32 S row -> fp16 P ----------
__global__ void __launch_bounds__(256)
softmax_h(const float* __restrict__ S, __half* __restrict__ P)
{
    __shared__ float red[8];
    const float* p = S + (size_t)blockIdx.x * LL;
    const int tid = threadIdx.x;
    const int lane = tid & 31, warp = tid >> 5;

    float4 v[4];
#pragma unroll
    for (int i = 0; i < 4; i++)
        v[i] = *(const float4*)(p + (i * 256 + tid) * 4);

    float m = -3.402823466e38f;
#pragma unroll
    for (int i = 0; i < 4; i++)
        m = fmaxf(m, fmaxf(fmaxf(v[i].x, v[i].y), fmaxf(v[i].z, v[i].w)));
#pragma unroll
    for (int s = 16; s > 0; s >>= 1)
        m = fmaxf(m, __shfl_xor_sync(0xffffffffu, m, s));
    if (lane == 0) red[warp] = m;
    __syncthreads();
    {
        float t = red[lane & 7];
#pragma unroll
        for (int s = 4; s > 0; s >>= 1)
            t = fmaxf(t, __shfl_xor_sync(0xffffffffu, t, s));
        m = t;
    }

    float sum = 0.0f;
#pragma unroll
    for (int i = 0; i < 4; i++) {
        v[i].x = __expf(v[i].x - m); v[i].y = __expf(v[i].y - m);
        v[i].z = __expf(v[i].z - m); v[i].w = __expf(v[i].w - m);
        sum += (v[i].x + v[i].y) + (v[i].z + v[i].w);
    }
#pragma unroll
    for (int s = 16; s > 0; s >>= 1)
        sum += __shfl_xor_sync(0xffffffffu, sum, s);
    __syncthreads();           // red[] reuse safe
    if (lane == 0) red[warp] = sum;
    __syncthreads();
    {
        float t = red[lane & 7];
#pragma unroll
        for (int s = 4; s > 0; s >>= 1)
            t += __shfl_xor_sync(0xffffffffu, t, s);
        sum = t;
    }
    const float inv = 1.0f / sum;

    __half2* ph = (__half2*)(P + (size_t)blockIdx.x * LL);
#pragma unroll
    for (int i = 0; i < 4; i++) {
        int idx = (i * 256 + tid) * 4;
        ph[idx / 2]     = __floats2half2_rn(v[i].x * inv, v[i].y * inv);
        ph[idx / 2 + 1] = __floats2half2_rn(v[i].z * inv, v[i].w * inv);
    }
}

// ---------------- orchestration ---------------------------------------------
extern "C" void kernel_launch(void* const* d_in, const int* in_sizes, int n_in,
                              void* d_out, int out_size)
{
    const float* X  = (const float*)d_in[0];
    const float* Wq = (const float*)d_in[1];
    const float* bq = (const float*)d_in[2];
    const float* Wk = (const float*)d_in[3];
    const float* bk = (const float*)d_in[4];
    const float* Wv = (const float*)d_in[5];
    const float* bv = (const float*)d_in[6];
    float* out = (float*)d_out;

    __half *Xh, *Xl, *Wth, *Wtl, *Qh, *Ql, *Kh, *Kl, *Vt, *P;
    float* S;
    cudaGetSymbolAddress((void**)&Xh, g_Xh);   cudaGetSymbolAddress((void**)&Xl, g_Xl);
    cudaGetSymbolAddress((void**)&Wth, g_Wth); cudaGetSymbolAddress((void**)&Wtl, g_Wtl);
    cudaGetSymbolAddress((void**)&Qh, g_Qh);   cudaGetSymbolAddress((void**)&Ql, g_Ql);
    cudaGetSymbolAddress((void**)&Kh, g_Kh);   cudaGetSymbolAddress((void**)&Kl, g_Kl);
    cudaGetSymbolAddress((void**)&Vt, g_Vt);
    cudaGetSymbolAddress((void**)&P, g_P);
    cudaGetSymbolAddress((void**)&S, g_S);

    cudaFuncSetAttribute(gemm_mma<0, 3>, cudaFuncAttributeMaxDynamicSharedMemorySize, SMEM3);
    cudaFuncSetAttribute(gemm_mma<2, 3>, cudaFuncAttributeMaxDynamicSharedMemorySize, SMEM3);
    cudaFuncSetAttribute(gemm_mma<2, 1>, cudaFuncAttributeMaxDynamicSharedMemorySize, SMEM1);

    EpiPtrs3 none{};

    // 1) split X into fp16 hi/lo
    {
        int n4 = ML * DD / 4;
        convert_split<<<(n4 + 255) / 256, 256>>>(X, Xh, Xl, n4);
    }
    // 2) transpose+split weights (one launch, z = q/k/v)
    {
        dim3 g(DD / 32, DD / 32, 3), b(32, 8);
        transW3<<<g, b>>>(Wq, Wk, Wv, Wth, Wtl);
    }
    // 3) projections, one launch; z=0/1 -> Q/K hi/lo, z=2 -> Vt transposed
    {
        EpiPtrs3 ep;
        ep.p[0] = {bq, Qh, Ql};
        ep.p[1] = {bk, Kh, Kl};
        ep.p[2] = {bv, Vt, nullptr};
        dim3 g(DD / 128, ML / 256, 3);
        gemm_mma<0, 3><<<g, 256, SMEM3>>>(Xh, Xl, Wth, Wtl, ep, nullptr,
            DD, DD, 0, (long long)DD * DD, 0);
    }
    // 4) logits: S[b] = Q[b] @ K[b]^T (fp16 3-term, fp32 out)
    {
        dim3 g(LL / 128, LL / 256, BB);
        gemm_mma<2, 3><<<g, 256, SMEM3>>>(Qh, Ql, Kh, Kl, none, S,
            DD, LL, (long long)LL * DD, (long long)LL * DD, (long long)LL * LL);
    }
    // 5) softmax rows -> single fp16 P
    softmax_h<<<ML, 256>>>(S, P);
    // 6) output: O[b] = P[b] @ Vt[b]^T (fp16 1-term, fp32 out)
    {
        dim3 g(DD / 128, LL / 256, BB);
        gemm_mma<2, 1><<<g, 256, SMEM1>>>(P, nullptr, Vt, nullptr, none, out,
            LL, DD, (long long)LL * LL, (long long)DD * LL, (long long)LL * DD);
    }
}